// round 10
// baseline (speedup 1.0000x reference)
#include <cuda_runtime.h>
#include <cuda_bf16.h>
#include <math.h>
#include <stdint.h>

#define BB 32
#define CC 512
#define LL 1024
#define NN (BB*LL)   /* 32768 tokens */
#define BROWS (BB * (LL + 2))   /* 32*1026 guard-row layout */

// ---------------- scratch (device globals; no allocation) ----------------
__device__ __align__(16) float        g_conv[(size_t)NN * CC];      // conv out [token][co] (67MB)
__device__ __align__(16) signed char  g_xq[(size_t)NN * CC];        // int8 activations [token][c]
__device__ __align__(16) float        g_stok[NN];                   // per-token dequant scale
__device__ __align__(16) float        g_mean[CC];
__device__ __align__(16) float        g_rstd[CC];
__device__ __align__(16) signed char  g_wq[CC * CC];                // ternary proj weights [o][c]
__device__ float                      g_wdq;                        // weight dequant scale
// conv GEMM operands, bf16 2-term split
__device__ __align__(16) __nv_bfloat16 g_wq2[(size_t)CC * 3072];    // weights [co][(split?1536:0)+tap*512+ci]
// activations: row = b*1026 + 1 + l (rows b*1026 and b*1026+1025 are zero guards)
__device__ __align__(16) __nv_bfloat16 g_bq[(size_t)BROWS * 1024];  // 67MB
// BN partial stats: one fp32 (sum, sumsq) slice per token-block (128 of them)
__device__ __align__(16) float g_psf[128 * CC];
__device__ __align__(16) float g_ps2f[128 * CC];
__device__ double g_wsum[64];

__device__ __forceinline__ float gelu_exact(float v) {
    return 0.5f * v * (1.0f + erff(v * 0.70710678118654752440f));
}

// ---------------- helpers ----------------
__device__ __forceinline__ uint32_t smem_u32(const void* p) {
    uint32_t a;
    asm("{ .reg .u64 t; cvta.to.shared.u64 t, %1; cvt.u32.u64 %0, t; }" : "=r"(a) : "l"(p));
    return a;
}
#define SWZ(o) ((o) ^ (((o) >> 3) & 0x70))

__device__ __forceinline__ void cp16(uint32_t dst, const void* src) {
    asm volatile("cp.async.cg.shared.global [%0], [%1], 16;" :: "r"(dst), "l"(src));
}
#define CP_COMMIT() asm volatile("cp.async.commit_group;" ::: "memory")
#define CP_WAIT0()  asm volatile("cp.async.wait_group 0;" ::: "memory")
#define CP_WAIT1()  asm volatile("cp.async.wait_group 1;" ::: "memory")
#define CP_WAIT2()  asm volatile("cp.async.wait_group 2;" ::: "memory")

#define LDSM_X4(r0, r1, r2, r3, addr) \
    asm volatile("ldmatrix.sync.aligned.m8n8.x4.shared.b16 {%0,%1,%2,%3}, [%4];" \
        : "=r"(r0), "=r"(r1), "=r"(r2), "=r"(r3) : "r"(addr))

__device__ __forceinline__ void mma16816(float* d, const uint32_t* a, uint32_t b0, uint32_t b1) {
    asm volatile("mma.sync.aligned.m16n8k16.row.col.f32.bf16.bf16.f32 "
        "{%0,%1,%2,%3}, {%4,%5,%6,%7}, {%8,%9}, {%0,%1,%2,%3};"
        : "+f"(d[0]), "+f"(d[1]), "+f"(d[2]), "+f"(d[3])
        : "r"(a[0]), "r"(a[1]), "r"(a[2]), "r"(a[3]), "r"(b0), "r"(b1));
}

__device__ __forceinline__ void imma16832(int* d, const uint32_t* a, uint32_t b0, uint32_t b1) {
    asm volatile("mma.sync.aligned.m16n8k32.row.col.s32.s8.s8.s32 "
        "{%0,%1,%2,%3}, {%4,%5,%6,%7}, {%8,%9}, {%0,%1,%2,%3};"
        : "+r"(d[0]), "+r"(d[1]), "+r"(d[2]), "+r"(d[3])
        : "r"(a[0]), "r"(a[1]), "r"(a[2]), "r"(a[3]), "r"(b0), "r"(b1));
}

// ---------------- proj weight quant: partial -> fin -> quantize ----------------
__global__ void prep_part_kernel(const float* __restrict__ w) {
    __shared__ double red[256];
    int t = threadIdx.x;
    int base = blockIdx.x * 4096;
    double s = 0.0;
    #pragma unroll 4
    for (int i = t; i < 4096; i += 256) s += (double)fabsf(w[base + i]);
    red[t] = s; __syncthreads();
    for (int o = 128; o > 0; o >>= 1) { if (t < o) red[t] += red[t + o]; __syncthreads(); }
    if (t == 0) g_wsum[blockIdx.x] = red[0];
}
__global__ void prep_fin_kernel() {
    __shared__ double red[64];
    int t = threadIdx.x;
    red[t] = g_wsum[t]; __syncthreads();
    for (int o = 32; o > 0; o >>= 1) { if (t < o) red[t] += red[t + o]; __syncthreads(); }
    if (t == 0) {
        float mean = (float)(red[0] * (1.0 / (double)(CC * CC)));
        g_wdq = fmaxf(mean, 1e-5f);
    }
}
__global__ void prep_quant_kernel(const float* __restrict__ w) {
    int i = blockIdx.x * 1024 + threadIdx.x;
    float sc = 1.0f / g_wdq;
    #pragma unroll
    for (int e = 0; e < 4; ++e) {
        int idx = i + e * 256;
        float q = rintf(w[idx] * sc);
        q = fminf(fmaxf(q, -1.0f), 1.0f);
        g_wq[idx] = (signed char)(int)q;
    }
}

// ---------------- conv weight bf16-split pack ----------------
__global__ void pack_w_kernel(const float* __restrict__ w) {   // w: [co][ci][3]
    int idx = blockIdx.x * 256 + threadIdx.x;
    if (idx >= CC * 1536) return;
    int co = idx / 1536, r = idx % 1536;
    int tap = r / 512, ci = r % 512;
    float f = w[((size_t)co * CC + ci) * 3 + tap];
    __nv_bfloat16 h = __float2bfloat16(f);
    __nv_bfloat16 l = __float2bfloat16(f - __bfloat162float(h));
    g_wq2[(size_t)co * 3072 + r]        = h;
    g_wq2[(size_t)co * 3072 + 1536 + r] = l;
}

// ---------------- activation transpose + bf16-split pack (guard-row layout) --------
__global__ __launch_bounds__(256) void pack_x_kernel(const float* __restrict__ x) {
    __shared__ float xs[128 * 65];
    int b   = blockIdx.z;
    int ci0 = blockIdx.y * 64;
    int l0  = blockIdx.x * 128;
    int t = threadIdx.x;

    for (int it = t; it < 64 * 128; it += 256) {
        int ci = it >> 7, c = it & 127;
        xs[c * 65 + ci] = x[((size_t)b * CC + ci0 + ci) * LL + l0 + c];
    }
    __syncthreads();

    for (int it = t; it < 1024; it += 256) {
        int tok = it >> 3, g = it & 7;
        __align__(16) __nv_bfloat16 hi[8], lo[8];
        #pragma unroll
        for (int e = 0; e < 8; ++e) {
            float f = xs[tok * 65 + g * 8 + e];
            __nv_bfloat16 h = __float2bfloat16(f);
            hi[e] = h;
            lo[e] = __float2bfloat16(f - __bfloat162float(h));
        }
        size_t row = (size_t)b * 1026 + 1 + l0 + tok;
        *(uint4*)(g_bq + row * 1024 + ci0 + g * 8)       = *(const uint4*)hi;
        *(uint4*)(g_bq + row * 1024 + 512 + ci0 + g * 8) = *(const uint4*)lo;
    }

    if (l0 == 0 && t < 16) {
        size_t row = (size_t)b * 1026;
        int col = (t >> 3) * 512 + ci0 + (t & 7) * 8;
        *(uint4*)(g_bq + row * 1024 + col) = make_uint4(0, 0, 0, 0);
    }
    if (l0 == (LL - 128) && t < 16) {
        size_t row = (size_t)b * 1026 + 1025;
        int col = (t >> 3) * 512 + ci0 + (t & 7) * 8;
        *(uint4*)(g_bq + row * 1024 + col) = make_uint4(0, 0, 0, 0);
    }
}

// ---------------- conv GEMM via mma.sync bf16 (3-pass split, fp32 acc) --------
// block tile 128 co x 256 tok; 8 warps of 64x64; 4-stage pipeline; fused BN partials.
static __device__ __forceinline__ void ld_chunk(uint32_t abuf, uint32_t bbuf,
                                                int idx, int co0, int browb, int t) {
    int p = idx / 24, ch = idx % 24;
    int tap = ch >> 3, cic = ch & 7;
    const __nv_bfloat16* ga = g_wq2 + (size_t)co0 * 3072 + ((p == 2) ? 1536 : 0) + ch * 64;
    const __nv_bfloat16* gb = g_bq + (size_t)(browb + tap) * 1024
                                   + ((p == 1) ? 512 : 0) + cic * 64;
    for (int it = t; it < 1024; it += 256) {
        int row = it >> 3, c = it & 7;
        cp16(abuf + SWZ(row * 128 + c * 16), ga + (size_t)row * 3072 + c * 8);
    }
    for (int it = t; it < 2048; it += 256) {
        int row = it >> 3, c = it & 7;
        cp16(bbuf + SWZ(row * 128 + c * 16), gb + (size_t)row * 1024 + c * 8);
    }
}

__global__ __launch_bounds__(256, 1) void conv_mma_kernel(const float* __restrict__ bias) {
    extern __shared__ char dsm_raw[];
    char* base = (char*)((((size_t)dsm_raw) + 1023) & ~(size_t)1023);
    uint32_t sb = smem_u32(base);
    // 4 stages, each: A 16KB @ +0, B 32KB @ +16384 (stage stride 48KB)
    uint32_t ab[4], bb[4];
    #pragma unroll
    for (int s = 0; s < 4; ++s) { ab[s] = sb + s * 49152; bb[s] = sb + s * 49152 + 16384; }
    __shared__ float bnred[8 * 64 * 2];

    int t = threadIdx.x, wid = t >> 5, lane = t & 31;
    int co0 = blockIdx.x * 128;
    int tok0 = blockIdx.y * 256;
    int bidx = tok0 >> 10;
    int l0 = tok0 & 1023;
    int browb = bidx * 1026 + l0;
    int wco  = (wid & 1) * 64;
    int wtok = (wid >> 1) * 64;

    float acc[4][8][4];
    #pragma unroll
    for (int i = 0; i < 4; ++i)
        #pragma unroll
        for (int j = 0; j < 8; ++j)
            #pragma unroll
            for (int e = 0; e < 4; ++e) acc[i][j][e] = 0.0f;

    int g = lane >> 3, r = lane & 7;
    uint32_t ao[4], aM[4], bo[4], bM[4];
    #pragma unroll
    for (int mt = 0; mt < 4; ++mt) {
        int row = wco + mt * 16 + (g & 1) * 8 + r;
        uint32_t o = row * 128 + (g >> 1) * 16;
        aM[mt] = (o >> 3) & 0x70; ao[mt] = o;
    }
    #pragma unroll
    for (int nt = 0; nt < 4; ++nt) {
        int row = wtok + nt * 16 + (g >> 1) * 8 + r;
        uint32_t o = row * 128 + (g & 1) * 16;
        bM[nt] = (o >> 3) & 0x70; bo[nt] = o;
    }

    ld_chunk(ab[0], bb[0], 0, co0, browb, t); CP_COMMIT();
    ld_chunk(ab[1], bb[1], 1, co0, browb, t); CP_COMMIT();

    for (int i = 0; i < 72; ++i) {
        if (i + 2 < 72) {
            ld_chunk(ab[(i + 2) & 3], bb[(i + 2) & 3], i + 2, co0, browb, t);
            CP_COMMIT();
            CP_WAIT2();
        } else if (i == 70) {
            CP_WAIT1();
        } else {
            CP_WAIT0();
        }
        __syncthreads();

        uint32_t abase = ab[i & 3], bbase = bb[i & 3];
        #pragma unroll
        for (int ks = 0; ks < 4; ++ks) {
            uint32_t Bf[4][4];
            #pragma unroll
            for (int nt = 0; nt < 4; ++nt)
                LDSM_X4(Bf[nt][0], Bf[nt][1], Bf[nt][2], Bf[nt][3],
                        bbase + (((bo[nt] + ks * 32)) ^ bM[nt]));
            #pragma unroll
            for (int mt = 0; mt < 4; ++mt) {
                uint32_t A[4];
                LDSM_X4(A[0], A[1], A[2], A[3],
                        abase + (((ao[mt] + ks * 32)) ^ aM[mt]));
                #pragma unroll
                for (int n8 = 0; n8 < 8; ++n8)
                    mma16816(acc[mt][n8], A,
                             Bf[n8 >> 1][(n8 & 1) * 2], Bf[n8 >> 1][(n8 & 1) * 2 + 1]);
            }
        }
    }
    __syncthreads();

    // ---- epilogue: bias add + store + fused BN partial sums ----
    float cs[4][2], cq[4][2];
    #pragma unroll
    for (int mt = 0; mt < 4; ++mt) { cs[mt][0] = cs[mt][1] = cq[mt][0] = cq[mt][1] = 0.0f; }

    #pragma unroll
    for (int mt = 0; mt < 4; ++mt) {
        int co = co0 + wco + mt * 16 + (lane >> 2);
        float bv0 = bias[co], bv1 = bias[co + 8];
        #pragma unroll
        for (int n8 = 0; n8 < 8; ++n8) {
            int tok = tok0 + wtok + n8 * 8 + (lane & 3) * 2;
            float v0 = acc[mt][n8][0] + bv0;
            float v1 = acc[mt][n8][1] + bv0;
            float v2 = acc[mt][n8][2] + bv1;
            float v3 = acc[mt][n8][3] + bv1;
            g_conv[(size_t)tok * CC + co]           = v0;
            g_conv[(size_t)(tok + 1) * CC + co]     = v1;
            g_conv[(size_t)tok * CC + co + 8]       = v2;
            g_conv[(size_t)(tok + 1) * CC + co + 8] = v3;
            cs[mt][0] += v0 + v1;  cq[mt][0] += v0 * v0 + v1 * v1;
            cs[mt][1] += v2 + v3;  cq[mt][1] += v2 * v2 + v3 * v3;
        }
    }
    #pragma unroll
    for (int off = 1; off <= 2; off <<= 1) {
        #pragma unroll
        for (int mt = 0; mt < 4; ++mt) {
            cs[mt][0] += __shfl_xor_sync(0xffffffff, cs[mt][0], off);
            cs[mt][1] += __shfl_xor_sync(0xffffffff, cs[mt][1], off);
            cq[mt][0] += __shfl_xor_sync(0xffffffff, cq[mt][0], off);
            cq[mt][1] += __shfl_xor_sync(0xffffffff, cq[mt][1], off);
        }
    }
    if ((lane & 3) == 0) {
        #pragma unroll
        for (int mt = 0; mt < 4; ++mt)
            #pragma unroll
            for (int h = 0; h < 2; ++h) {
                int ci = mt * 16 + (lane >> 2) + 8 * h;
                bnred[(wid * 64 + ci) * 2]     = cs[mt][h];
                bnred[(wid * 64 + ci) * 2 + 1] = cq[mt][h];
            }
    }
    __syncthreads();
    {
        int half = t >> 7, ci = (t >> 1) & 63, val = t & 1;
        float s = bnred[((half)     * 64 + ci) * 2 + val]
                + bnred[((half + 2) * 64 + ci) * 2 + val]
                + bnred[((half + 4) * 64 + ci) * 2 + val]
                + bnred[((half + 6) * 64 + ci) * 2 + val];
        int co = co0 + half * 64 + ci;
        if (val == 0) g_psf[blockIdx.y * CC + co]  = s;
        else          g_ps2f[blockIdx.y * CC + co] = s;
    }
}

// ---------------- BN finalize: deterministic double reduction over 128 slices ------
__global__ void bn_fin_kernel() {
    int co = threadIdx.x;
    double a = 0.0, b2 = 0.0;
    #pragma unroll 4
    for (int s = 0; s < 128; ++s) {
        a  += (double)g_psf[s * CC + co];
        b2 += (double)g_ps2f[s * CC + co];
    }
    double m = a / (double)NN;
    double var = b2 / (double)NN - m * m;
    g_mean[co] = (float)m;
    g_rstd[co] = (float)(1.0 / sqrt(var + 1e-5));
}

// ---------------- BN apply + GELU + per-token int8 quant (warp per token) ----------------
__global__ __launch_bounds__(256) void quant_kernel(const float* __restrict__ gamma,
                                                    const float* __restrict__ beta) {
    int t = threadIdx.x, w = t >> 5, lane = t & 31;
    size_t token = (size_t)blockIdx.x * 8 + w;
    int c0 = lane * 16;
    float vals[16];
    float mx = 0.0f;
    #pragma unroll
    for (int i = 0; i < 4; ++i) {
        float4 cv = *(const float4*)(g_conv + token * CC + c0 + i * 4);
        float4 m4 = *(const float4*)(g_mean + c0 + i * 4);
        float4 r4 = *(const float4*)(g_rstd + c0 + i * 4);
        float4 gm = *(const float4*)(gamma + c0 + i * 4);
        float4 bt = *(const float4*)(beta + c0 + i * 4);
        float a[4] = { (cv.x - m4.x) * r4.x * gm.x + bt.x,
                       (cv.y - m4.y) * r4.y * gm.y + bt.y,
                       (cv.z - m4.z) * r4.z * gm.z + bt.z,
                       (cv.w - m4.w) * r4.w * gm.w + bt.w };
        #pragma unroll
        for (int e = 0; e < 4; ++e) {
            float gg = gelu_exact(a[e]);
            vals[i * 4 + e] = gg;
            mx = fmaxf(mx, fabsf(gg));
        }
    }
    #pragma unroll
    for (int off = 16; off > 0; off >>= 1)
        mx = fmaxf(mx, __shfl_xor_sync(0xffffffff, mx, off));
    float clip = fmaxf(mx, 1e-5f);
    if (lane == 0) g_stok[token] = clip * (1.0f / 127.0f);
    float sc = 127.0f / clip;
    int pk[4];
    #pragma unroll
    for (int i = 0; i < 4; ++i) {
        int b0 = 0;
        #pragma unroll
        for (int e = 0; e < 4; ++e) {
            float q = rintf(vals[i * 4 + e] * sc);
            q = fminf(fmaxf(q, -128.0f), 127.0f);
            b0 |= ((int)q & 0xff) << (e * 8);
        }
        pk[i] = b0;
    }
    *(int4*)(g_xq + token * CC + c0) = make_int4(pk[0], pk[1], pk[2], pk[3]);
}

// ---------------- int8 proj GEMM via IMMA: 128co x 256tok blocks, 4-buffer loads ----
static __device__ __forceinline__ void ld_chunk_p(uint32_t abuf, uint32_t bbuf,
                                                  int idx, int co0, int tok0, int t) {
    const signed char* ga = g_wq + (size_t)co0 * 512 + idx * 128;   // A rows = co (128)
    const signed char* gb = g_xq + (size_t)tok0 * 512 + idx * 128;  // B rows = tok (256)
    for (int it = t; it < 1024; it += 256) {
        int row = it >> 3, c = it & 7;
        cp16(abuf + SWZ(row * 128 + c * 16), ga + (size_t)row * 512 + c * 16);
    }
    for (int it = t; it < 2048; it += 256) {
        int row = it >> 3, c = it & 7;
        cp16(bbuf + SWZ(row * 128 + c * 16), gb + (size_t)row * 512 + c * 16);
    }
}

__global__ __launch_bounds__(256, 1) void proj_mma_kernel(const float* __restrict__ xres,
                                                          float* __restrict__ out) {
    extern __shared__ char dsm_raw[];
    char* base = (char*)((((size_t)dsm_raw) + 1023) & ~(size_t)1023);
    uint32_t sb = smem_u32(base);
    uint32_t ab[4], bb[4];
    #pragma unroll
    for (int s = 0; s < 4; ++s) { ab[s] = sb + s * 49152; bb[s] = sb + s * 49152 + 16384; }

    int t = threadIdx.x, wid = t >> 5, lane = t & 31;
    int co0  = blockIdx.x * 128;
    int tok0 = blockIdx.y * 256;
    int wco  = (wid & 1) * 64;
    int wtok = (wid >> 1) * 64;

    int acc[4][8][4];
    #pragma unroll
    for (int i = 0; i < 4; ++i)
        #pragma unroll
        for (int j = 0; j < 8; ++j)
            #pragma unroll
            for (int e = 0; e < 4; ++e) acc[i][j][e] = 0;

    int g = lane >> 3, r = lane & 7;
    uint32_t ao[4], aM[4], bo[4], bM[4];
    #pragma unroll
    for (int mt = 0; mt < 4; ++mt) {
        int row = wco + mt * 16 + (g & 1) * 8 + r;
        uint32_t o = row * 128 + (g >> 1) * 16;
        aM[mt] = (o >> 3) & 0x70; ao[mt] = o;
    }
    #pragma unroll
    for (int nt = 0; nt < 4; ++nt) {
        int row = wtok + nt * 16 + (g >> 1) * 8 + r;
        uint32_t o = row * 128 + (g & 1) * 16;
        bM[nt] = (o >> 3) & 0x70; bo[nt] = o;
    }

    // load all 4 K-chunks upfront into 4 buffers
    #pragma unroll
    for (int i = 0; i < 4; ++i) {
        ld_chunk_p(ab[i], bb[i], i, co0, tok0, t);
        CP_COMMIT();
    }

    #pragma unroll
    for (int i = 0; i < 4; ++i) {
        if (i == 0)      CP_WAIT2();        // wait for chunk 0 (3 pending ok... need <=3) 
        else if (i == 1) CP_WAIT2();
        else if (i == 2) CP_WAIT1();
        else             CP_WAIT0();
        __syncthreads();

        uint32_t abase = ab[i], bbase = bb[i];
        #pragma unroll
        for (int ks = 0; ks < 4; ++ks) {
            uint32_t Bf[4][4];
            #pragma unroll
            for (int nt = 0; nt < 4; ++nt)
                LDSM_X4(Bf[nt][0], Bf[nt][1], Bf[nt][2], Bf[nt][3],
                        bbase + (((bo[nt] + ks * 32)) ^ bM[nt]));
            #pragma unroll
            for (int mt = 0; mt < 4; ++mt) {
                uint32_t A[4];
                LDSM_X4(A[0], A[1], A[2], A[3],
                        abase + (((ao[mt] + ks * 32)) ^ aM[mt]));
                #pragma unroll
                for (int n8 = 0; n8 < 8; ++n8)
                    imma16832(acc[mt][n8], A,
                              Bf[n8 >> 1][(n8 & 1) * 2], Bf[n8 >> 1][(n8 & 1) * 2 + 1]);
            }
        }
    }

    // epilogue: acc[mt][n8] = {(co,tok),(co,tok+1),(co+8,tok),(co+8,tok+1)}
    float wdq = g_wdq;
    #pragma unroll
    for (int n8 = 0; n8 < 8; ++n8) {
        int tok = tok0 + wtok + n8 * 8 + (lane & 3) * 2;
        float2 sp = *(const float2*)&g_stok[tok];
        float s0 = sp.x * wdq, s1 = sp.y * wdq;
        int b = tok >> 10, l = tok & 1023;
        #pragma unroll
        for (int mt = 0; mt < 4; ++mt) {
            int co = co0 + wco + mt * 16 + (lane >> 2);
            size_t base0 = (((size_t)b * CC + co) << 10) + l;
            size_t base1 = base0 + ((size_t)8 << 10);
            float2 r0 = *(const float2*)&xres[base0];
            float2 r1 = *(const float2*)&xres[base1];
            float2 o0, o1;
            o0.x = gelu_exact((float)acc[mt][n8][0] * s0) + r0.x;
            o0.y = gelu_exact((float)acc[mt][n8][1] * s1) + r0.y;
            o1.x = gelu_exact((float)acc[mt][n8][2] * s0) + r1.x;
            o1.y = gelu_exact((float)acc[mt][n8][3] * s1) + r1.y;
            *(float2*)&out[base0] = o0;
            *(float2*)&out[base1] = o1;
        }
    }
}

// ---------------- launch ----------------
extern "C" void kernel_launch(void* const* d_in, const int* in_sizes, int n_in,
                              void* d_out, int out_size) {
    (void)in_sizes; (void)n_in; (void)out_size;
    const float* x      = (const float*)d_in[0];   // [32,512,1024]
    const float* conv_w = (const float*)d_in[1];   // [512,512,3]
    const float* conv_b = (const float*)d_in[2];   // [512]
    const float* gamma  = (const float*)d_in[3];   // [512]
    const float* beta   = (const float*)d_in[4];   // [512]
    const float* proj_w = (const float*)d_in[5];   // [512,512]
    float* out = (float*)d_out;

    static int inited = 0;
    static cudaStream_t s2 = 0;
    static cudaEvent_t evF = 0, evJ = 0;
    if (!inited) {
        cudaFuncSetAttribute(conv_mma_kernel, cudaFuncAttributeMaxDynamicSharedMemorySize, 197632);
        cudaFuncSetAttribute(proj_mma_kernel, cudaFuncAttributeMaxDynamicSharedMemorySize, 197632);
        if (cudaStreamCreateWithFlags(&s2, cudaStreamNonBlocking) != cudaSuccess) s2 = 0;
        cudaEventCreateWithFlags(&evF, cudaEventDisableTiming);
        cudaEventCreateWithFlags(&evJ, cudaEventDisableTiming);
        inited = 1;
    }

    // fork: proj-weight prep on side stream (joined before proj)
    cudaEventRecord(evF, 0);
    if (s2) cudaStreamWaitEvent(s2, evF, 0);
    prep_part_kernel<<<64, 256, 0, s2>>>(proj_w);
    prep_fin_kernel<<<1, 64, 0, s2>>>();
    prep_quant_kernel<<<256, 256, 0, s2>>>(proj_w);
    if (s2) cudaEventRecord(evJ, s2);

    pack_w_kernel<<<(CC * 1536 + 255) / 256, 256>>>(conv_w);
    pack_x_kernel<<<dim3(8, 8, 32), 256>>>(x);

    conv_mma_kernel<<<dim3(4, 128), 256, 197632>>>(conv_b);

    bn_fin_kernel<<<1, 512>>>();
    quant_kernel<<<NN / 8, 256>>>(gamma, beta);

    if (s2) cudaStreamWaitEvent(0, evJ, 0);
    proj_mma_kernel<<<dim3(4, 128), 256, 197632>>>(x, out);
}

// round 11
// speedup vs baseline: 1.0772x; 1.0772x over previous
#include <cuda_runtime.h>
#include <cuda_bf16.h>
#include <math.h>
#include <stdint.h>

#define BB 32
#define CC 512
#define LL 1024
#define NN (BB*LL)   /* 32768 tokens */
#define BROWS (BB * (LL + 2))   /* 32*1026 guard-row layout */

// ---------------- scratch (device globals; no allocation) ----------------
__device__ __align__(16) float        g_conv[(size_t)NN * CC];      // conv out [token][co] (67MB)
__device__ __align__(16) signed char  g_xq[(size_t)NN * CC];        // int8 activations [token][c]
__device__ __align__(16) float        g_stok[NN];                   // per-token dequant scale
__device__ __align__(16) float        g_mean[CC];
__device__ __align__(16) float        g_rstd[CC];
__device__ __align__(16) signed char  g_wq[CC * CC];                // ternary proj weights [o][c]
__device__ float                      g_wdq;                        // weight dequant scale
// conv GEMM operands, bf16 2-term split
__device__ __align__(16) __nv_bfloat16 g_wq2[(size_t)CC * 3072];    // weights [co][(split?1536:0)+tap*512+ci]
// activations: row = b*1026 + 1 + l (rows b*1026 and b*1026+1025 are zero guards)
__device__ __align__(16) __nv_bfloat16 g_bq[(size_t)BROWS * 1024];  // 67MB
// BN partial stats: one fp32 (sum, sumsq) slice per token-block (128 of them)
__device__ __align__(16) float g_psf[128 * CC];
__device__ __align__(16) float g_ps2f[128 * CC];
__device__ double g_wsum[64];

__device__ __forceinline__ float gelu_exact(float v) {
    return 0.5f * v * (1.0f + erff(v * 0.70710678118654752440f));
}

// ---------------- helpers ----------------
__device__ __forceinline__ uint32_t smem_u32(const void* p) {
    uint32_t a;
    asm("{ .reg .u64 t; cvta.to.shared.u64 t, %1; cvt.u32.u64 %0, t; }" : "=r"(a) : "l"(p));
    return a;
}
#define SWZ(o) ((o) ^ (((o) >> 3) & 0x70))

__device__ __forceinline__ void cp16(uint32_t dst, const void* src) {
    asm volatile("cp.async.cg.shared.global [%0], [%1], 16;" :: "r"(dst), "l"(src));
}
#define CP_COMMIT() asm volatile("cp.async.commit_group;" ::: "memory")
#define CP_WAIT0()  asm volatile("cp.async.wait_group 0;" ::: "memory")
#define CP_WAIT1()  asm volatile("cp.async.wait_group 1;" ::: "memory")
#define CP_WAIT2()  asm volatile("cp.async.wait_group 2;" ::: "memory")

#define LDSM_X4(r0, r1, r2, r3, addr) \
    asm volatile("ldmatrix.sync.aligned.m8n8.x4.shared.b16 {%0,%1,%2,%3}, [%4];" \
        : "=r"(r0), "=r"(r1), "=r"(r2), "=r"(r3) : "r"(addr))

__device__ __forceinline__ void mma16816(float* d, const uint32_t* a, uint32_t b0, uint32_t b1) {
    asm volatile("mma.sync.aligned.m16n8k16.row.col.f32.bf16.bf16.f32 "
        "{%0,%1,%2,%3}, {%4,%5,%6,%7}, {%8,%9}, {%0,%1,%2,%3};"
        : "+f"(d[0]), "+f"(d[1]), "+f"(d[2]), "+f"(d[3])
        : "r"(a[0]), "r"(a[1]), "r"(a[2]), "r"(a[3]), "r"(b0), "r"(b1));
}

__device__ __forceinline__ void imma16832(int* d, const uint32_t* a, uint32_t b0, uint32_t b1) {
    asm volatile("mma.sync.aligned.m16n8k32.row.col.s32.s8.s8.s32 "
        "{%0,%1,%2,%3}, {%4,%5,%6,%7}, {%8,%9}, {%0,%1,%2,%3};"
        : "+r"(d[0]), "+r"(d[1]), "+r"(d[2]), "+r"(d[3])
        : "r"(a[0]), "r"(a[1]), "r"(a[2]), "r"(a[3]), "r"(b0), "r"(b1));
}

// ---------------- proj weight quant: partial -> fin -> quantize ----------------
__global__ void prep_part_kernel(const float* __restrict__ w) {
    __shared__ double red[256];
    int t = threadIdx.x;
    int base = blockIdx.x * 4096;
    double s = 0.0;
    #pragma unroll 4
    for (int i = t; i < 4096; i += 256) s += (double)fabsf(w[base + i]);
    red[t] = s; __syncthreads();
    for (int o = 128; o > 0; o >>= 1) { if (t < o) red[t] += red[t + o]; __syncthreads(); }
    if (t == 0) g_wsum[blockIdx.x] = red[0];
}
__global__ void prep_fin_kernel() {
    __shared__ double red[64];
    int t = threadIdx.x;
    red[t] = g_wsum[t]; __syncthreads();
    for (int o = 32; o > 0; o >>= 1) { if (t < o) red[t] += red[t + o]; __syncthreads(); }
    if (t == 0) {
        float mean = (float)(red[0] * (1.0 / (double)(CC * CC)));
        g_wdq = fmaxf(mean, 1e-5f);
    }
}
__global__ void prep_quant_kernel(const float* __restrict__ w) {
    int i = blockIdx.x * 1024 + threadIdx.x;
    float sc = 1.0f / g_wdq;
    #pragma unroll
    for (int e = 0; e < 4; ++e) {
        int idx = i + e * 256;
        float q = rintf(w[idx] * sc);
        q = fminf(fmaxf(q, -1.0f), 1.0f);
        g_wq[idx] = (signed char)(int)q;
    }
}

// ---------------- conv weight bf16-split pack ----------------
__global__ void pack_w_kernel(const float* __restrict__ w) {   // w: [co][ci][3]
    int idx = blockIdx.x * 256 + threadIdx.x;
    if (idx >= CC * 1536) return;
    int co = idx / 1536, r = idx % 1536;
    int tap = r / 512, ci = r % 512;
    float f = w[((size_t)co * CC + ci) * 3 + tap];
    __nv_bfloat16 h = __float2bfloat16(f);
    __nv_bfloat16 l = __float2bfloat16(f - __bfloat162float(h));
    g_wq2[(size_t)co * 3072 + r]        = h;
    g_wq2[(size_t)co * 3072 + 1536 + r] = l;
}

// ---------------- activation transpose + bf16-split pack (guard-row layout) --------
__global__ __launch_bounds__(256) void pack_x_kernel(const float* __restrict__ x) {
    __shared__ float xs[128 * 65];
    int b   = blockIdx.z;
    int ci0 = blockIdx.y * 64;
    int l0  = blockIdx.x * 128;
    int t = threadIdx.x;

    for (int it = t; it < 64 * 128; it += 256) {
        int ci = it >> 7, c = it & 127;
        xs[c * 65 + ci] = x[((size_t)b * CC + ci0 + ci) * LL + l0 + c];
    }
    __syncthreads();

    for (int it = t; it < 1024; it += 256) {
        int tok = it >> 3, g = it & 7;
        __align__(16) __nv_bfloat16 hi[8], lo[8];
        #pragma unroll
        for (int e = 0; e < 8; ++e) {
            float f = xs[tok * 65 + g * 8 + e];
            __nv_bfloat16 h = __float2bfloat16(f);
            hi[e] = h;
            lo[e] = __float2bfloat16(f - __bfloat162float(h));
        }
        size_t row = (size_t)b * 1026 + 1 + l0 + tok;
        *(uint4*)(g_bq + row * 1024 + ci0 + g * 8)       = *(const uint4*)hi;
        *(uint4*)(g_bq + row * 1024 + 512 + ci0 + g * 8) = *(const uint4*)lo;
    }

    if (l0 == 0 && t < 16) {
        size_t row = (size_t)b * 1026;
        int col = (t >> 3) * 512 + ci0 + (t & 7) * 8;
        *(uint4*)(g_bq + row * 1024 + col) = make_uint4(0, 0, 0, 0);
    }
    if (l0 == (LL - 128) && t < 16) {
        size_t row = (size_t)b * 1026 + 1025;
        int col = (t >> 3) * 512 + ci0 + (t & 7) * 8;
        *(uint4*)(g_bq + row * 1024 + col) = make_uint4(0, 0, 0, 0);
    }
}

// ---------------- conv GEMM via mma.sync bf16 (3-pass split, fp32 acc) --------
// block tile 128 co x 256 tok; 8 warps of 64x64; 4-stage pipeline; fused BN partials.
static __device__ __forceinline__ void ld_chunk(uint32_t abuf, uint32_t bbuf,
                                                int idx, int co0, int browb, int t) {
    int p = idx / 24, ch = idx % 24;
    int tap = ch >> 3, cic = ch & 7;
    const __nv_bfloat16* ga = g_wq2 + (size_t)co0 * 3072 + ((p == 2) ? 1536 : 0) + ch * 64;
    const __nv_bfloat16* gb = g_bq + (size_t)(browb + tap) * 1024
                                   + ((p == 1) ? 512 : 0) + cic * 64;
    for (int it = t; it < 1024; it += 256) {
        int row = it >> 3, c = it & 7;
        cp16(abuf + SWZ(row * 128 + c * 16), ga + (size_t)row * 3072 + c * 8);
    }
    for (int it = t; it < 2048; it += 256) {
        int row = it >> 3, c = it & 7;
        cp16(bbuf + SWZ(row * 128 + c * 16), gb + (size_t)row * 1024 + c * 8);
    }
}

__global__ __launch_bounds__(256, 1) void conv_mma_kernel(const float* __restrict__ bias) {
    extern __shared__ char dsm_raw[];
    char* base = (char*)((((size_t)dsm_raw) + 1023) & ~(size_t)1023);
    uint32_t sb = smem_u32(base);
    uint32_t ab[4], bb[4];
    #pragma unroll
    for (int s = 0; s < 4; ++s) { ab[s] = sb + s * 49152; bb[s] = sb + s * 49152 + 16384; }
    __shared__ float bnred[8 * 64 * 2];

    int t = threadIdx.x, wid = t >> 5, lane = t & 31;
    int co0 = blockIdx.x * 128;
    int tok0 = blockIdx.y * 256;
    int bidx = tok0 >> 10;
    int l0 = tok0 & 1023;
    int browb = bidx * 1026 + l0;
    int wco  = (wid & 1) * 64;
    int wtok = (wid >> 1) * 64;

    float acc[4][8][4];
    #pragma unroll
    for (int i = 0; i < 4; ++i)
        #pragma unroll
        for (int j = 0; j < 8; ++j)
            #pragma unroll
            for (int e = 0; e < 4; ++e) acc[i][j][e] = 0.0f;

    int g = lane >> 3, r = lane & 7;
    uint32_t ao[4], aM[4], bo[4], bM[4];
    #pragma unroll
    for (int mt = 0; mt < 4; ++mt) {
        int row = wco + mt * 16 + (g & 1) * 8 + r;
        uint32_t o = row * 128 + (g >> 1) * 16;
        aM[mt] = (o >> 3) & 0x70; ao[mt] = o;
    }
    #pragma unroll
    for (int nt = 0; nt < 4; ++nt) {
        int row = wtok + nt * 16 + (g >> 1) * 8 + r;
        uint32_t o = row * 128 + (g & 1) * 16;
        bM[nt] = (o >> 3) & 0x70; bo[nt] = o;
    }

    ld_chunk(ab[0], bb[0], 0, co0, browb, t); CP_COMMIT();
    ld_chunk(ab[1], bb[1], 1, co0, browb, t); CP_COMMIT();

    for (int i = 0; i < 72; ++i) {
        if (i + 2 < 72) {
            ld_chunk(ab[(i + 2) & 3], bb[(i + 2) & 3], i + 2, co0, browb, t);
            CP_COMMIT();
            CP_WAIT2();
        } else if (i == 70) {
            CP_WAIT1();
        } else {
            CP_WAIT0();
        }
        __syncthreads();

        uint32_t abase = ab[i & 3], bbase = bb[i & 3];
        #pragma unroll
        for (int ks = 0; ks < 4; ++ks) {
            uint32_t Bf[4][4];
            #pragma unroll
            for (int nt = 0; nt < 4; ++nt)
                LDSM_X4(Bf[nt][0], Bf[nt][1], Bf[nt][2], Bf[nt][3],
                        bbase + (((bo[nt] + ks * 32)) ^ bM[nt]));
            #pragma unroll
            for (int mt = 0; mt < 4; ++mt) {
                uint32_t A[4];
                LDSM_X4(A[0], A[1], A[2], A[3],
                        abase + (((ao[mt] + ks * 32)) ^ aM[mt]));
                #pragma unroll
                for (int n8 = 0; n8 < 8; ++n8)
                    mma16816(acc[mt][n8], A,
                             Bf[n8 >> 1][(n8 & 1) * 2], Bf[n8 >> 1][(n8 & 1) * 2 + 1]);
            }
        }
    }
    __syncthreads();

    // ---- epilogue: bias add + store + fused BN partial sums ----
    float cs[4][2], cq[4][2];
    #pragma unroll
    for (int mt = 0; mt < 4; ++mt) { cs[mt][0] = cs[mt][1] = cq[mt][0] = cq[mt][1] = 0.0f; }

    #pragma unroll
    for (int mt = 0; mt < 4; ++mt) {
        int co = co0 + wco + mt * 16 + (lane >> 2);
        float bv0 = bias[co], bv1 = bias[co + 8];
        #pragma unroll
        for (int n8 = 0; n8 < 8; ++n8) {
            int tok = tok0 + wtok + n8 * 8 + (lane & 3) * 2;
            float v0 = acc[mt][n8][0] + bv0;
            float v1 = acc[mt][n8][1] + bv0;
            float v2 = acc[mt][n8][2] + bv1;
            float v3 = acc[mt][n8][3] + bv1;
            g_conv[(size_t)tok * CC + co]           = v0;
            g_conv[(size_t)(tok + 1) * CC + co]     = v1;
            g_conv[(size_t)tok * CC + co + 8]       = v2;
            g_conv[(size_t)(tok + 1) * CC + co + 8] = v3;
            cs[mt][0] += v0 + v1;  cq[mt][0] += v0 * v0 + v1 * v1;
            cs[mt][1] += v2 + v3;  cq[mt][1] += v2 * v2 + v3 * v3;
        }
    }
    #pragma unroll
    for (int off = 1; off <= 2; off <<= 1) {
        #pragma unroll
        for (int mt = 0; mt < 4; ++mt) {
            cs[mt][0] += __shfl_xor_sync(0xffffffff, cs[mt][0], off);
            cs[mt][1] += __shfl_xor_sync(0xffffffff, cs[mt][1], off);
            cq[mt][0] += __shfl_xor_sync(0xffffffff, cq[mt][0], off);
            cq[mt][1] += __shfl_xor_sync(0xffffffff, cq[mt][1], off);
        }
    }
    if ((lane & 3) == 0) {
        #pragma unroll
        for (int mt = 0; mt < 4; ++mt)
            #pragma unroll
            for (int h = 0; h < 2; ++h) {
                int ci = mt * 16 + (lane >> 2) + 8 * h;
                bnred[(wid * 64 + ci) * 2]     = cs[mt][h];
                bnred[(wid * 64 + ci) * 2 + 1] = cq[mt][h];
            }
    }
    __syncthreads();
    {
        int half = t >> 7, ci = (t >> 1) & 63, val = t & 1;
        float s = bnred[((half)     * 64 + ci) * 2 + val]
                + bnred[((half + 2) * 64 + ci) * 2 + val]
                + bnred[((half + 4) * 64 + ci) * 2 + val]
                + bnred[((half + 6) * 64 + ci) * 2 + val];
        int co = co0 + half * 64 + ci;
        if (val == 0) g_psf[blockIdx.y * CC + co]  = s;
        else          g_ps2f[blockIdx.y * CC + co] = s;
    }
}

// ---------------- BN finalize: deterministic double reduction over 128 slices ------
__global__ void bn_fin_kernel() {
    int co = threadIdx.x;
    double a = 0.0, b2 = 0.0;
    #pragma unroll 4
    for (int s = 0; s < 128; ++s) {
        a  += (double)g_psf[s * CC + co];
        b2 += (double)g_ps2f[s * CC + co];
    }
    double m = a / (double)NN;
    double var = b2 / (double)NN - m * m;
    g_mean[co] = (float)m;
    g_rstd[co] = (float)(1.0 / sqrt(var + 1e-5));
}

// ---------------- BN apply + GELU + per-token int8 quant (warp per token) ----------------
__global__ __launch_bounds__(256) void quant_kernel(const float* __restrict__ gamma,
                                                    const float* __restrict__ beta) {
    int t = threadIdx.x, w = t >> 5, lane = t & 31;
    size_t token = (size_t)blockIdx.x * 8 + w;
    int c0 = lane * 16;
    float vals[16];
    float mx = 0.0f;
    #pragma unroll
    for (int i = 0; i < 4; ++i) {
        float4 cv = *(const float4*)(g_conv + token * CC + c0 + i * 4);
        float4 m4 = *(const float4*)(g_mean + c0 + i * 4);
        float4 r4 = *(const float4*)(g_rstd + c0 + i * 4);
        float4 gm = *(const float4*)(gamma + c0 + i * 4);
        float4 bt = *(const float4*)(beta + c0 + i * 4);
        float a[4] = { (cv.x - m4.x) * r4.x * gm.x + bt.x,
                       (cv.y - m4.y) * r4.y * gm.y + bt.y,
                       (cv.z - m4.z) * r4.z * gm.z + bt.z,
                       (cv.w - m4.w) * r4.w * gm.w + bt.w };
        #pragma unroll
        for (int e = 0; e < 4; ++e) {
            float gg = gelu_exact(a[e]);
            vals[i * 4 + e] = gg;
            mx = fmaxf(mx, fabsf(gg));
        }
    }
    #pragma unroll
    for (int off = 16; off > 0; off >>= 1)
        mx = fmaxf(mx, __shfl_xor_sync(0xffffffff, mx, off));
    float clip = fmaxf(mx, 1e-5f);
    if (lane == 0) g_stok[token] = clip * (1.0f / 127.0f);
    float sc = 127.0f / clip;
    int pk[4];
    #pragma unroll
    for (int i = 0; i < 4; ++i) {
        int b0 = 0;
        #pragma unroll
        for (int e = 0; e < 4; ++e) {
            float q = rintf(vals[i * 4 + e] * sc);
            q = fminf(fmaxf(q, -128.0f), 127.0f);
            b0 |= ((int)q & 0xff) << (e * 8);
        }
        pk[i] = b0;
    }
    *(int4*)(g_xq + token * CC + c0) = make_int4(pk[0], pk[1], pk[2], pk[3]);
}

// ---------------- int8 proj GEMM via IMMA (exact): 128co x 128tok, 2 blocks/SM -----
static __device__ __forceinline__ void ld_chunk_p(uint32_t abuf, uint32_t bbuf,
                                                  int idx, int co0, int tok0, int t) {
    const signed char* ga = g_wq + (size_t)co0 * 512 + idx * 128;   // A rows = co
    const signed char* gb = g_xq + (size_t)tok0 * 512 + idx * 128;  // B rows = tok
    for (int it = t; it < 1024; it += 256) {
        int row = it >> 3, c = it & 7;
        cp16(abuf + SWZ(row * 128 + c * 16), ga + (size_t)row * 512 + c * 16);
    }
    for (int it = t; it < 1024; it += 256) {
        int row = it >> 3, c = it & 7;
        cp16(bbuf + SWZ(row * 128 + c * 16), gb + (size_t)row * 512 + c * 16);
    }
}

__global__ __launch_bounds__(256) void proj_mma_kernel(const float* __restrict__ xres,
                                                       float* __restrict__ out) {
    extern __shared__ char dsm_raw[];
    char* base = (char*)((((size_t)dsm_raw) + 1023) & ~(size_t)1023);
    uint32_t sb = smem_u32(base);
    uint32_t ab[2] = { sb,             sb + 32768 };
    uint32_t bb[2] = { sb + 16384,     sb + 49152 };

    int t = threadIdx.x, wid = t >> 5, lane = t & 31;
    int co0  = blockIdx.x * 128;
    int tok0 = blockIdx.y * 128;
    int wco  = (wid & 1) * 64;     // warp covers 64 co (m)
    int wtok = (wid >> 1) * 32;    // warp covers 32 tokens (n)

    int acc[4][4][4];
    #pragma unroll
    for (int i = 0; i < 4; ++i)
        #pragma unroll
        for (int j = 0; j < 4; ++j)
            #pragma unroll
            for (int e = 0; e < 4; ++e) acc[i][j][e] = 0;

    int g = lane >> 3, r = lane & 7;
    uint32_t ao[4], aM[4], bo[2], bM[2];
    #pragma unroll
    for (int mt = 0; mt < 4; ++mt) {
        int row = wco + mt * 16 + (g & 1) * 8 + r;
        uint32_t o = row * 128 + (g >> 1) * 16;
        aM[mt] = (o >> 3) & 0x70; ao[mt] = o;
    }
    #pragma unroll
    for (int nt = 0; nt < 2; ++nt) {
        int row = wtok + nt * 16 + (g >> 1) * 8 + r;
        uint32_t o = row * 128 + (g & 1) * 16;
        bM[nt] = (o >> 3) & 0x70; bo[nt] = o;
    }

    ld_chunk_p(ab[0], bb[0], 0, co0, tok0, t);
    CP_COMMIT();

    for (int i = 0; i < 4; ++i) {
        int cur = i & 1;
        if (i + 1 < 4) {
            ld_chunk_p(ab[cur ^ 1], bb[cur ^ 1], i + 1, co0, tok0, t);
            CP_COMMIT();
            CP_WAIT1();
        } else {
            CP_WAIT0();
        }
        __syncthreads();

        uint32_t abase = ab[cur], bbase = bb[cur];
        #pragma unroll
        for (int ks = 0; ks < 4; ++ks) {
            uint32_t A[4][4], Bf[2][4];
            #pragma unroll
            for (int mt = 0; mt < 4; ++mt)
                LDSM_X4(A[mt][0], A[mt][1], A[mt][2], A[mt][3],
                        abase + (((ao[mt] + ks * 32)) ^ aM[mt]));
            #pragma unroll
            for (int nt = 0; nt < 2; ++nt)
                LDSM_X4(Bf[nt][0], Bf[nt][1], Bf[nt][2], Bf[nt][3],
                        bbase + (((bo[nt] + ks * 32)) ^ bM[nt]));
            #pragma unroll
            for (int mt = 0; mt < 4; ++mt)
                #pragma unroll
                for (int n8 = 0; n8 < 4; ++n8)
                    imma16832(acc[mt][n8], A[mt],
                              Bf[n8 >> 1][(n8 & 1) * 2], Bf[n8 >> 1][(n8 & 1) * 2 + 1]);
        }
        __syncthreads();
    }

    // epilogue: acc[mt][n8] = {(co,tok),(co,tok+1),(co+8,tok),(co+8,tok+1)}
    float wdq = g_wdq;
    #pragma unroll
    for (int n8 = 0; n8 < 4; ++n8) {
        int tok = tok0 + wtok + n8 * 8 + (lane & 3) * 2;
        float2 sp = *(const float2*)&g_stok[tok];
        float s0 = sp.x * wdq, s1 = sp.y * wdq;
        int b = tok >> 10, l = tok & 1023;
        #pragma unroll
        for (int mt = 0; mt < 4; ++mt) {
            int co = co0 + wco + mt * 16 + (lane >> 2);
            size_t base0 = (((size_t)b * CC + co) << 10) + l;
            size_t base1 = base0 + ((size_t)8 << 10);
            float2 r0 = *(const float2*)&xres[base0];
            float2 r1 = *(const float2*)&xres[base1];
            float2 o0, o1;
            o0.x = gelu_exact((float)acc[mt][n8][0] * s0) + r0.x;
            o0.y = gelu_exact((float)acc[mt][n8][1] * s1) + r0.y;
            o1.x = gelu_exact((float)acc[mt][n8][2] * s0) + r1.x;
            o1.y = gelu_exact((float)acc[mt][n8][3] * s1) + r1.y;
            *(float2*)&out[base0] = o0;
            *(float2*)&out[base1] = o1;
        }
    }
}

// ---------------- launch ----------------
extern "C" void kernel_launch(void* const* d_in, const int* in_sizes, int n_in,
                              void* d_out, int out_size) {
    (void)in_sizes; (void)n_in; (void)out_size;
    const float* x      = (const float*)d_in[0];   // [32,512,1024]
    const float* conv_w = (const float*)d_in[1];   // [512,512,3]
    const float* conv_b = (const float*)d_in[2];   // [512]
    const float* gamma  = (const float*)d_in[3];   // [512]
    const float* beta   = (const float*)d_in[4];   // [512]
    const float* proj_w = (const float*)d_in[5];   // [512,512]
    float* out = (float*)d_out;

    static int inited = 0;
    static cudaStream_t s2 = 0;
    static cudaEvent_t evF = 0, evJ = 0;
    if (!inited) {
        cudaFuncSetAttribute(conv_mma_kernel, cudaFuncAttributeMaxDynamicSharedMemorySize, 197632);
        cudaFuncSetAttribute(proj_mma_kernel, cudaFuncAttributeMaxDynamicSharedMemorySize, 66560);
        if (cudaStreamCreateWithFlags(&s2, cudaStreamNonBlocking) != cudaSuccess) s2 = 0;
        cudaEventCreateWithFlags(&evF, cudaEventDisableTiming);
        cudaEventCreateWithFlags(&evJ, cudaEventDisableTiming);
        inited = 1;
    }

    // fork: proj-weight prep on side stream (joined before proj)
    cudaEventRecord(evF, 0);
    if (s2) cudaStreamWaitEvent(s2, evF, 0);
    prep_part_kernel<<<64, 256, 0, s2>>>(proj_w);
    prep_fin_kernel<<<1, 64, 0, s2>>>();
    prep_quant_kernel<<<256, 256, 0, s2>>>(proj_w);
    if (s2) cudaEventRecord(evJ, s2);

    pack_w_kernel<<<(CC * 1536 + 255) / 256, 256>>>(conv_w);
    pack_x_kernel<<<dim3(8, 8, 32), 256>>>(x);

    conv_mma_kernel<<<dim3(4, 128), 256, 197632>>>(conv_b);

    bn_fin_kernel<<<1, 512>>>();
    quant_kernel<<<NN / 8, 256>>>(gamma, beta);

    if (s2) cudaStreamWaitEvent(0, evJ, 0);
    proj_mma_kernel<<<dim3(4, 256), 256, 66560>>>(x, out);
}

// round 12
// speedup vs baseline: 1.0820x; 1.0045x over previous
#include <cuda_runtime.h>
#include <cuda_bf16.h>
#include <math.h>
#include <stdint.h>

#define BB 32
#define CC 512
#define LL 1024
#define NN (BB*LL)   /* 32768 tokens */
#define BROWS (BB * (LL + 2))   /* 32*1026 guard-row layout */

// ---------------- scratch (device globals; no allocation) ----------------
__device__ __align__(16) float        g_conv[(size_t)NN * CC];      // conv out [token][co] (67MB)
__device__ __align__(16) signed char  g_xq[(size_t)NN * CC];        // int8 activations [token][c]
__device__ __align__(16) float        g_stok[NN];                   // per-token dequant scale
__device__ __align__(16) float        g_mean[CC];
__device__ __align__(16) float        g_rstd[CC];
__device__ __align__(16) signed char  g_wq[CC * CC];                // ternary proj weights [o][c]
__device__ float                      g_wdq;                        // weight dequant scale
// conv GEMM operands, bf16 2-term split
__device__ __align__(16) __nv_bfloat16 g_wq2[(size_t)CC * 3072];    // weights [co][(split?1536:0)+tap*512+ci]
// activations: row = b*1026 + 1 + l (rows b*1026 and b*1026+1025 are zero guards)
__device__ __align__(16) __nv_bfloat16 g_bq[(size_t)BROWS * 1024];  // 67MB
// BN partial stats: one fp32 (sum, sumsq) slice per token-block (128 of them)
__device__ __align__(16) float g_psf[128 * CC];
__device__ __align__(16) float g_ps2f[128 * CC];
__device__ double g_wsum[64];

__device__ __forceinline__ float gelu_exact(float v) {
    return 0.5f * v * (1.0f + erff(v * 0.70710678118654752440f));
}

// ---------------- helpers ----------------
__device__ __forceinline__ uint32_t smem_u32(const void* p) {
    uint32_t a;
    asm("{ .reg .u64 t; cvta.to.shared.u64 t, %1; cvt.u32.u64 %0, t; }" : "=r"(a) : "l"(p));
    return a;
}
#define SWZ(o) ((o) ^ (((o) >> 3) & 0x70))

__device__ __forceinline__ void cp16(uint32_t dst, const void* src) {
    asm volatile("cp.async.cg.shared.global [%0], [%1], 16;" :: "r"(dst), "l"(src));
}
#define CP_COMMIT() asm volatile("cp.async.commit_group;" ::: "memory")
#define CP_WAIT0()  asm volatile("cp.async.wait_group 0;" ::: "memory")
#define CP_WAIT1()  asm volatile("cp.async.wait_group 1;" ::: "memory")
#define CP_WAIT2()  asm volatile("cp.async.wait_group 2;" ::: "memory")

#define LDSM_X4(r0, r1, r2, r3, addr) \
    asm volatile("ldmatrix.sync.aligned.m8n8.x4.shared.b16 {%0,%1,%2,%3}, [%4];" \
        : "=r"(r0), "=r"(r1), "=r"(r2), "=r"(r3) : "r"(addr))

__device__ __forceinline__ void mma16816(float* d, const uint32_t* a, uint32_t b0, uint32_t b1) {
    asm volatile("mma.sync.aligned.m16n8k16.row.col.f32.bf16.bf16.f32 "
        "{%0,%1,%2,%3}, {%4,%5,%6,%7}, {%8,%9}, {%0,%1,%2,%3};"
        : "+f"(d[0]), "+f"(d[1]), "+f"(d[2]), "+f"(d[3])
        : "r"(a[0]), "r"(a[1]), "r"(a[2]), "r"(a[3]), "r"(b0), "r"(b1));
}

__device__ __forceinline__ void imma16832(int* d, const uint32_t* a, uint32_t b0, uint32_t b1) {
    asm volatile("mma.sync.aligned.m16n8k32.row.col.s32.s8.s8.s32 "
        "{%0,%1,%2,%3}, {%4,%5,%6,%7}, {%8,%9}, {%0,%1,%2,%3};"
        : "+r"(d[0]), "+r"(d[1]), "+r"(d[2]), "+r"(d[3])
        : "r"(a[0]), "r"(a[1]), "r"(a[2]), "r"(a[3]), "r"(b0), "r"(b1));
}

// ---------------- proj weight quant: partial -> fin -> quantize ----------------
__global__ void prep_part_kernel(const float* __restrict__ w) {
    __shared__ double red[256];
    int t = threadIdx.x;
    int base = blockIdx.x * 4096;
    double s = 0.0;
    #pragma unroll 4
    for (int i = t; i < 4096; i += 256) s += (double)fabsf(w[base + i]);
    red[t] = s; __syncthreads();
    for (int o = 128; o > 0; o >>= 1) { if (t < o) red[t] += red[t + o]; __syncthreads(); }
    if (t == 0) g_wsum[blockIdx.x] = red[0];
}
__global__ void prep_fin_kernel() {
    __shared__ double red[64];
    int t = threadIdx.x;
    red[t] = g_wsum[t]; __syncthreads();
    for (int o = 32; o > 0; o >>= 1) { if (t < o) red[t] += red[t + o]; __syncthreads(); }
    if (t == 0) {
        float mean = (float)(red[0] * (1.0 / (double)(CC * CC)));
        g_wdq = fmaxf(mean, 1e-5f);
    }
}
__global__ void prep_quant_kernel(const float* __restrict__ w) {
    int i = blockIdx.x * 1024 + threadIdx.x;
    float sc = 1.0f / g_wdq;
    #pragma unroll
    for (int e = 0; e < 4; ++e) {
        int idx = i + e * 256;
        float q = rintf(w[idx] * sc);
        q = fminf(fmaxf(q, -1.0f), 1.0f);
        g_wq[idx] = (signed char)(int)q;
    }
}

// ---------------- conv weight bf16-split pack ----------------
__global__ void pack_w_kernel(const float* __restrict__ w) {   // w: [co][ci][3]
    int idx = blockIdx.x * 256 + threadIdx.x;
    if (idx >= CC * 1536) return;
    int co = idx / 1536, r = idx % 1536;
    int tap = r / 512, ci = r % 512;
    float f = w[((size_t)co * CC + ci) * 3 + tap];
    __nv_bfloat16 h = __float2bfloat16(f);
    __nv_bfloat16 l = __float2bfloat16(f - __bfloat162float(h));
    g_wq2[(size_t)co * 3072 + r]        = h;
    g_wq2[(size_t)co * 3072 + 1536 + r] = l;
}

// ---------------- activation transpose + bf16-split pack (guard-row layout) --------
__global__ __launch_bounds__(256) void pack_x_kernel(const float* __restrict__ x) {
    __shared__ float xs[128 * 65];
    int b   = blockIdx.z;
    int ci0 = blockIdx.y * 64;
    int l0  = blockIdx.x * 128;
    int t = threadIdx.x;

    for (int it = t; it < 64 * 128; it += 256) {
        int ci = it >> 7, c = it & 127;
        xs[c * 65 + ci] = x[((size_t)b * CC + ci0 + ci) * LL + l0 + c];
    }
    __syncthreads();

    for (int it = t; it < 1024; it += 256) {
        int tok = it >> 3, g = it & 7;
        __align__(16) __nv_bfloat16 hi[8], lo[8];
        #pragma unroll
        for (int e = 0; e < 8; ++e) {
            float f = xs[tok * 65 + g * 8 + e];
            __nv_bfloat16 h = __float2bfloat16(f);
            hi[e] = h;
            lo[e] = __float2bfloat16(f - __bfloat162float(h));
        }
        size_t row = (size_t)b * 1026 + 1 + l0 + tok;
        *(uint4*)(g_bq + row * 1024 + ci0 + g * 8)       = *(const uint4*)hi;
        *(uint4*)(g_bq + row * 1024 + 512 + ci0 + g * 8) = *(const uint4*)lo;
    }

    if (l0 == 0 && t < 16) {
        size_t row = (size_t)b * 1026;
        int col = (t >> 3) * 512 + ci0 + (t & 7) * 8;
        *(uint4*)(g_bq + row * 1024 + col) = make_uint4(0, 0, 0, 0);
    }
    if (l0 == (LL - 128) && t < 16) {
        size_t row = (size_t)b * 1026 + 1025;
        int col = (t >> 3) * 512 + ci0 + (t & 7) * 8;
        *(uint4*)(g_bq + row * 1024 + col) = make_uint4(0, 0, 0, 0);
    }
}

// ---------------- conv GEMM via mma.sync bf16 (3-pass split, fp32 acc) --------
// 128 co x 256 tok; 8 warps of 64x64; 4-stage cp.async pipeline; ks-pipelined frags.
static __device__ __forceinline__ void ld_chunk(uint32_t abuf, uint32_t bbuf,
                                                int idx, int co0, int browb, int t) {
    int p = idx / 24, ch = idx % 24;
    int tap = ch >> 3, cic = ch & 7;
    const __nv_bfloat16* ga = g_wq2 + (size_t)co0 * 3072 + ((p == 2) ? 1536 : 0) + ch * 64;
    const __nv_bfloat16* gb = g_bq + (size_t)(browb + tap) * 1024
                                   + ((p == 1) ? 512 : 0) + cic * 64;
    for (int it = t; it < 1024; it += 256) {
        int row = it >> 3, c = it & 7;
        cp16(abuf + SWZ(row * 128 + c * 16), ga + (size_t)row * 3072 + c * 8);
    }
    for (int it = t; it < 2048; it += 256) {
        int row = it >> 3, c = it & 7;
        cp16(bbuf + SWZ(row * 128 + c * 16), gb + (size_t)row * 1024 + c * 8);
    }
}

__global__ __launch_bounds__(256, 1) void conv_mma_kernel(const float* __restrict__ bias) {
    extern __shared__ char dsm_raw[];
    char* base = (char*)((((size_t)dsm_raw) + 1023) & ~(size_t)1023);
    uint32_t sb = smem_u32(base);
    uint32_t ab[4], bb[4];
    #pragma unroll
    for (int s = 0; s < 4; ++s) { ab[s] = sb + s * 49152; bb[s] = sb + s * 49152 + 16384; }
    __shared__ float bnred[8 * 64 * 2];

    int t = threadIdx.x, wid = t >> 5, lane = t & 31;
    int co0 = blockIdx.x * 128;
    int tok0 = blockIdx.y * 256;
    int bidx = tok0 >> 10;
    int l0 = tok0 & 1023;
    int browb = bidx * 1026 + l0;
    int wco  = (wid & 1) * 64;
    int wtok = (wid >> 1) * 64;

    float acc[4][8][4];
    #pragma unroll
    for (int i = 0; i < 4; ++i)
        #pragma unroll
        for (int j = 0; j < 8; ++j)
            #pragma unroll
            for (int e = 0; e < 4; ++e) acc[i][j][e] = 0.0f;

    int g = lane >> 3, r = lane & 7;
    uint32_t ao[4], aM[4], bo[4], bM[4];
    #pragma unroll
    for (int mt = 0; mt < 4; ++mt) {
        int row = wco + mt * 16 + (g & 1) * 8 + r;
        uint32_t o = row * 128 + (g >> 1) * 16;
        aM[mt] = (o >> 3) & 0x70; ao[mt] = o;
    }
    #pragma unroll
    for (int nt = 0; nt < 4; ++nt) {
        int row = wtok + nt * 16 + (g >> 1) * 8 + r;
        uint32_t o = row * 128 + (g & 1) * 16;
        bM[nt] = (o >> 3) & 0x70; bo[nt] = o;
    }

    ld_chunk(ab[0], bb[0], 0, co0, browb, t); CP_COMMIT();
    ld_chunk(ab[1], bb[1], 1, co0, browb, t); CP_COMMIT();

    // ks-pipelined fragment double buffers
    uint32_t Af[2][4][4], Bg[2][4][4];

    for (int i = 0; i < 72; ++i) {
        if (i + 2 < 72) {
            ld_chunk(ab[(i + 2) & 3], bb[(i + 2) & 3], i + 2, co0, browb, t);
            CP_COMMIT();
            CP_WAIT2();
        } else if (i == 70) {
            CP_WAIT1();
        } else {
            CP_WAIT0();
        }
        __syncthreads();

        uint32_t abase = ab[i & 3], bbase = bb[i & 3];

        // prime ks=0 fragments
        #pragma unroll
        for (int nt = 0; nt < 4; ++nt)
            LDSM_X4(Bg[0][nt][0], Bg[0][nt][1], Bg[0][nt][2], Bg[0][nt][3],
                    bbase + ((bo[nt]) ^ bM[nt]));
        #pragma unroll
        for (int mt = 0; mt < 4; ++mt)
            LDSM_X4(Af[0][mt][0], Af[0][mt][1], Af[0][mt][2], Af[0][mt][3],
                    abase + ((ao[mt]) ^ aM[mt]));

        #pragma unroll
        for (int ks = 0; ks < 4; ++ks) {
            int cb = ks & 1;
            if (ks < 3) {
                int nb = cb ^ 1;
                #pragma unroll
                for (int nt = 0; nt < 4; ++nt)
                    LDSM_X4(Bg[nb][nt][0], Bg[nb][nt][1], Bg[nb][nt][2], Bg[nb][nt][3],
                            bbase + (((bo[nt] + (ks + 1) * 32)) ^ bM[nt]));
                #pragma unroll
                for (int mt = 0; mt < 4; ++mt)
                    LDSM_X4(Af[nb][mt][0], Af[nb][mt][1], Af[nb][mt][2], Af[nb][mt][3],
                            abase + (((ao[mt] + (ks + 1) * 32)) ^ aM[mt]));
            }
            #pragma unroll
            for (int mt = 0; mt < 4; ++mt)
                #pragma unroll
                for (int n8 = 0; n8 < 8; ++n8)
                    mma16816(acc[mt][n8], Af[cb][mt],
                             Bg[cb][n8 >> 1][(n8 & 1) * 2], Bg[cb][n8 >> 1][(n8 & 1) * 2 + 1]);
        }
    }
    __syncthreads();

    // ---- epilogue: bias add + store + fused BN partial sums ----
    float cs[4][2], cq[4][2];
    #pragma unroll
    for (int mt = 0; mt < 4; ++mt) { cs[mt][0] = cs[mt][1] = cq[mt][0] = cq[mt][1] = 0.0f; }

    #pragma unroll
    for (int mt = 0; mt < 4; ++mt) {
        int co = co0 + wco + mt * 16 + (lane >> 2);
        float bv0 = bias[co], bv1 = bias[co + 8];
        #pragma unroll
        for (int n8 = 0; n8 < 8; ++n8) {
            int tok = tok0 + wtok + n8 * 8 + (lane & 3) * 2;
            float v0 = acc[mt][n8][0] + bv0;
            float v1 = acc[mt][n8][1] + bv0;
            float v2 = acc[mt][n8][2] + bv1;
            float v3 = acc[mt][n8][3] + bv1;
            g_conv[(size_t)tok * CC + co]           = v0;
            g_conv[(size_t)(tok + 1) * CC + co]     = v1;
            g_conv[(size_t)tok * CC + co + 8]       = v2;
            g_conv[(size_t)(tok + 1) * CC + co + 8] = v3;
            cs[mt][0] += v0 + v1;  cq[mt][0] += v0 * v0 + v1 * v1;
            cs[mt][1] += v2 + v3;  cq[mt][1] += v2 * v2 + v3 * v3;
        }
    }
    #pragma unroll
    for (int off = 1; off <= 2; off <<= 1) {
        #pragma unroll
        for (int mt = 0; mt < 4; ++mt) {
            cs[mt][0] += __shfl_xor_sync(0xffffffff, cs[mt][0], off);
            cs[mt][1] += __shfl_xor_sync(0xffffffff, cs[mt][1], off);
            cq[mt][0] += __shfl_xor_sync(0xffffffff, cq[mt][0], off);
            cq[mt][1] += __shfl_xor_sync(0xffffffff, cq[mt][1], off);
        }
    }
    if ((lane & 3) == 0) {
        #pragma unroll
        for (int mt = 0; mt < 4; ++mt)
            #pragma unroll
            for (int h = 0; h < 2; ++h) {
                int ci = mt * 16 + (lane >> 2) + 8 * h;
                bnred[(wid * 64 + ci) * 2]     = cs[mt][h];
                bnred[(wid * 64 + ci) * 2 + 1] = cq[mt][h];
            }
    }
    __syncthreads();
    {
        int half = t >> 7, ci = (t >> 1) & 63, val = t & 1;
        float s = bnred[((half)     * 64 + ci) * 2 + val]
                + bnred[((half + 2) * 64 + ci) * 2 + val]
                + bnred[((half + 4) * 64 + ci) * 2 + val]
                + bnred[((half + 6) * 64 + ci) * 2 + val];
        int co = co0 + half * 64 + ci;
        if (val == 0) g_psf[blockIdx.y * CC + co]  = s;
        else          g_ps2f[blockIdx.y * CC + co] = s;
    }
}

// ---------------- BN finalize: deterministic double reduction over 128 slices ------
__global__ void bn_fin_kernel() {
    int co = threadIdx.x;
    double a = 0.0, b2 = 0.0;
    #pragma unroll 4
    for (int s = 0; s < 128; ++s) {
        a  += (double)g_psf[s * CC + co];
        b2 += (double)g_ps2f[s * CC + co];
    }
    double m = a / (double)NN;
    double var = b2 / (double)NN - m * m;
    g_mean[co] = (float)m;
    g_rstd[co] = (float)(1.0 / sqrt(var + 1e-5));
}

// ---------------- BN apply + GELU + per-token int8 quant (warp per token) ----------------
__global__ __launch_bounds__(256) void quant_kernel(const float* __restrict__ gamma,
                                                    const float* __restrict__ beta) {
    int t = threadIdx.x, w = t >> 5, lane = t & 31;
    size_t token = (size_t)blockIdx.x * 8 + w;
    int c0 = lane * 16;
    float vals[16];
    float mx = 0.0f;
    #pragma unroll
    for (int i = 0; i < 4; ++i) {
        float4 cv = *(const float4*)(g_conv + token * CC + c0 + i * 4);
        float4 m4 = *(const float4*)(g_mean + c0 + i * 4);
        float4 r4 = *(const float4*)(g_rstd + c0 + i * 4);
        float4 gm = *(const float4*)(gamma + c0 + i * 4);
        float4 bt = *(const float4*)(beta + c0 + i * 4);
        float a[4] = { (cv.x - m4.x) * r4.x * gm.x + bt.x,
                       (cv.y - m4.y) * r4.y * gm.y + bt.y,
                       (cv.z - m4.z) * r4.z * gm.z + bt.z,
                       (cv.w - m4.w) * r4.w * gm.w + bt.w };
        #pragma unroll
        for (int e = 0; e < 4; ++e) {
            float gg = gelu_exact(a[e]);
            vals[i * 4 + e] = gg;
            mx = fmaxf(mx, fabsf(gg));
        }
    }
    #pragma unroll
    for (int off = 16; off > 0; off >>= 1)
        mx = fmaxf(mx, __shfl_xor_sync(0xffffffff, mx, off));
    float clip = fmaxf(mx, 1e-5f);
    if (lane == 0) g_stok[token] = clip * (1.0f / 127.0f);
    float sc = 127.0f / clip;
    int pk[4];
    #pragma unroll
    for (int i = 0; i < 4; ++i) {
        int b0 = 0;
        #pragma unroll
        for (int e = 0; e < 4; ++e) {
            float q = rintf(vals[i * 4 + e] * sc);
            q = fminf(fmaxf(q, -128.0f), 127.0f);
            b0 |= ((int)q & 0xff) << (e * 8);
        }
        pk[i] = b0;
    }
    *(int4*)(g_xq + token * CC + c0) = make_int4(pk[0], pk[1], pk[2], pk[3]);
}

// ---------------- int8 proj GEMM via IMMA (exact): 128co x 128tok, 2 blocks/SM -----
static __device__ __forceinline__ void ld_chunk_p(uint32_t abuf, uint32_t bbuf,
                                                  int idx, int co0, int tok0, int t) {
    const signed char* ga = g_wq + (size_t)co0 * 512 + idx * 128;   // A rows = co
    const signed char* gb = g_xq + (size_t)tok0 * 512 + idx * 128;  // B rows = tok
    for (int it = t; it < 1024; it += 256) {
        int row = it >> 3, c = it & 7;
        cp16(abuf + SWZ(row * 128 + c * 16), ga + (size_t)row * 512 + c * 16);
    }
    for (int it = t; it < 1024; it += 256) {
        int row = it >> 3, c = it & 7;
        cp16(bbuf + SWZ(row * 128 + c * 16), gb + (size_t)row * 512 + c * 16);
    }
}

__global__ __launch_bounds__(256) void proj_mma_kernel(const float* __restrict__ xres,
                                                       float* __restrict__ out) {
    extern __shared__ char dsm_raw[];
    char* base = (char*)((((size_t)dsm_raw) + 1023) & ~(size_t)1023);
    uint32_t sb = smem_u32(base);
    uint32_t ab[2] = { sb,             sb + 32768 };
    uint32_t bb[2] = { sb + 16384,     sb + 49152 };

    int t = threadIdx.x, wid = t >> 5, lane = t & 31;
    int co0  = blockIdx.x * 128;
    int tok0 = blockIdx.y * 128;
    int wco  = (wid & 1) * 64;     // warp covers 64 co (m)
    int wtok = (wid >> 1) * 32;    // warp covers 32 tokens (n)

    int acc[4][4][4];
    #pragma unroll
    for (int i = 0; i < 4; ++i)
        #pragma unroll
        for (int j = 0; j < 4; ++j)
            #pragma unroll
            for (int e = 0; e < 4; ++e) acc[i][j][e] = 0;

    int g = lane >> 3, r = lane & 7;
    uint32_t ao[4], aM[4], bo[2], bM[2];
    #pragma unroll
    for (int mt = 0; mt < 4; ++mt) {
        int row = wco + mt * 16 + (g & 1) * 8 + r;
        uint32_t o = row * 128 + (g >> 1) * 16;
        aM[mt] = (o >> 3) & 0x70; ao[mt] = o;
    }
    #pragma unroll
    for (int nt = 0; nt < 2; ++nt) {
        int row = wtok + nt * 16 + (g >> 1) * 8 + r;
        uint32_t o = row * 128 + (g & 1) * 16;
        bM[nt] = (o >> 3) & 0x70; bo[nt] = o;
    }

    ld_chunk_p(ab[0], bb[0], 0, co0, tok0, t);
    CP_COMMIT();

    for (int i = 0; i < 4; ++i) {
        int cur = i & 1;
        if (i + 1 < 4) {
            ld_chunk_p(ab[cur ^ 1], bb[cur ^ 1], i + 1, co0, tok0, t);
            CP_COMMIT();
            CP_WAIT1();
        } else {
            CP_WAIT0();
        }
        __syncthreads();

        uint32_t abase = ab[cur], bbase = bb[cur];
        #pragma unroll
        for (int ks = 0; ks < 4; ++ks) {
            uint32_t A[4][4], Bf[2][4];
            #pragma unroll
            for (int mt = 0; mt < 4; ++mt)
                LDSM_X4(A[mt][0], A[mt][1], A[mt][2], A[mt][3],
                        abase + (((ao[mt] + ks * 32)) ^ aM[mt]));
            #pragma unroll
            for (int nt = 0; nt < 2; ++nt)
                LDSM_X4(Bf[nt][0], Bf[nt][1], Bf[nt][2], Bf[nt][3],
                        bbase + (((bo[nt] + ks * 32)) ^ bM[nt]));
            #pragma unroll
            for (int mt = 0; mt < 4; ++mt)
                #pragma unroll
                for (int n8 = 0; n8 < 4; ++n8)
                    imma16832(acc[mt][n8], A[mt],
                              Bf[n8 >> 1][(n8 & 1) * 2], Bf[n8 >> 1][(n8 & 1) * 2 + 1]);
        }
        __syncthreads();
    }

    // epilogue: acc[mt][n8] = {(co,tok),(co,tok+1),(co+8,tok),(co+8,tok+1)}
    float wdq = g_wdq;
    #pragma unroll
    for (int n8 = 0; n8 < 4; ++n8) {
        int tok = tok0 + wtok + n8 * 8 + (lane & 3) * 2;
        float2 sp = *(const float2*)&g_stok[tok];
        float s0 = sp.x * wdq, s1 = sp.y * wdq;
        int b = tok >> 10, l = tok & 1023;
        #pragma unroll
        for (int mt = 0; mt < 4; ++mt) {
            int co = co0 + wco + mt * 16 + (lane >> 2);
            size_t base0 = (((size_t)b * CC + co) << 10) + l;
            size_t base1 = base0 + ((size_t)8 << 10);
            float2 r0 = *(const float2*)&xres[base0];
            float2 r1 = *(const float2*)&xres[base1];
            float2 o0, o1;
            o0.x = gelu_exact((float)acc[mt][n8][0] * s0) + r0.x;
            o0.y = gelu_exact((float)acc[mt][n8][1] * s1) + r0.y;
            o1.x = gelu_exact((float)acc[mt][n8][2] * s0) + r1.x;
            o1.y = gelu_exact((float)acc[mt][n8][3] * s1) + r1.y;
            *(float2*)&out[base0] = o0;
            *(float2*)&out[base1] = o1;
        }
    }
}

// ---------------- launch ----------------
extern "C" void kernel_launch(void* const* d_in, const int* in_sizes, int n_in,
                              void* d_out, int out_size) {
    (void)in_sizes; (void)n_in; (void)out_size;
    const float* x      = (const float*)d_in[0];   // [32,512,1024]
    const float* conv_w = (const float*)d_in[1];   // [512,512,3]
    const float* conv_b = (const float*)d_in[2];   // [512]
    const float* gamma  = (const float*)d_in[3];   // [512]
    const float* beta   = (const float*)d_in[4];   // [512]
    const float* proj_w = (const float*)d_in[5];   // [512,512]
    float* out = (float*)d_out;

    static int inited = 0;
    static cudaStream_t s2 = 0;
    static cudaEvent_t evF = 0, evJ = 0;
    if (!inited) {
        cudaFuncSetAttribute(conv_mma_kernel, cudaFuncAttributeMaxDynamicSharedMemorySize, 197632);
        cudaFuncSetAttribute(proj_mma_kernel, cudaFuncAttributeMaxDynamicSharedMemorySize, 66560);
        if (cudaStreamCreateWithFlags(&s2, cudaStreamNonBlocking) != cudaSuccess) s2 = 0;
        cudaEventCreateWithFlags(&evF, cudaEventDisableTiming);
        cudaEventCreateWithFlags(&evJ, cudaEventDisableTiming);
        inited = 1;
    }

    // fork: proj-weight prep on side stream (joined before proj)
    cudaEventRecord(evF, 0);
    if (s2) cudaStreamWaitEvent(s2, evF, 0);
    prep_part_kernel<<<64, 256, 0, s2>>>(proj_w);
    prep_fin_kernel<<<1, 64, 0, s2>>>();
    prep_quant_kernel<<<256, 256, 0, s2>>>(proj_w);
    if (s2) cudaEventRecord(evJ, s2);

    pack_w_kernel<<<(CC * 1536 + 255) / 256, 256>>>(conv_w);
    pack_x_kernel<<<dim3(8, 8, 32), 256>>>(x);

    conv_mma_kernel<<<dim3(4, 128), 256, 197632>>>(conv_b);

    bn_fin_kernel<<<1, 512>>>();
    quant_kernel<<<NN / 8, 256>>>(gamma, beta);

    if (s2) cudaStreamWaitEvent(0, evJ, 0);
    proj_mma_kernel<<<dim3(4, 256), 256, 66560>>>(x, out);
}

// round 13
// speedup vs baseline: 1.0869x; 1.0045x over previous
#include <cuda_runtime.h>
#include <cuda_bf16.h>
#include <math.h>
#include <stdint.h>

#define BB 32
#define CC 512
#define LL 1024
#define NN (BB*LL)   /* 32768 tokens */
#define BROWS (BB * (LL + 2))   /* 32*1026 guard-row layout */

// ---------------- scratch (device globals; no allocation) ----------------
__device__ __align__(16) float        g_conv[(size_t)NN * CC];      // conv out [token][co] (67MB)
__device__ __align__(16) signed char  g_xq[(size_t)NN * CC];        // int8 activations [token][c]
__device__ __align__(16) float        g_stok[NN];                   // per-token dequant scale
__device__ __align__(16) float        g_mean[CC];
__device__ __align__(16) float        g_rstd[CC];
__device__ __align__(16) signed char  g_wq[CC * CC];                // ternary proj weights [o][c]
__device__ float                      g_wdq;                        // weight dequant scale
// conv GEMM operands, bf16 2-term split
__device__ __align__(16) __nv_bfloat16 g_wq2[(size_t)CC * 3072];    // weights [co][(split?1536:0)+tap*512+ci]
// activations: row = b*1026 + 1 + l (rows b*1026 and b*1026+1025 are zero guards)
__device__ __align__(16) __nv_bfloat16 g_bq[(size_t)BROWS * 1024];  // 67MB
// BN partial stats: one fp32 (sum, sumsq) slice per token-block (256 of them)
__device__ __align__(16) float g_psf[256 * CC];
__device__ __align__(16) float g_ps2f[256 * CC];
__device__ double g_wsum[64];

__device__ __forceinline__ float gelu_exact(float v) {
    return 0.5f * v * (1.0f + erff(v * 0.70710678118654752440f));
}

// ---------------- helpers ----------------
__device__ __forceinline__ uint32_t smem_u32(const void* p) {
    uint32_t a;
    asm("{ .reg .u64 t; cvta.to.shared.u64 t, %1; cvt.u32.u64 %0, t; }" : "=r"(a) : "l"(p));
    return a;
}
#define SWZ(o) ((o) ^ (((o) >> 3) & 0x70))

__device__ __forceinline__ void cp16(uint32_t dst, const void* src) {
    asm volatile("cp.async.cg.shared.global [%0], [%1], 16;" :: "r"(dst), "l"(src));
}
#define CP_COMMIT() asm volatile("cp.async.commit_group;" ::: "memory")
#define CP_WAIT0()  asm volatile("cp.async.wait_group 0;" ::: "memory")
#define CP_WAIT1()  asm volatile("cp.async.wait_group 1;" ::: "memory")

#define LDSM_X4(r0, r1, r2, r3, addr) \
    asm volatile("ldmatrix.sync.aligned.m8n8.x4.shared.b16 {%0,%1,%2,%3}, [%4];" \
        : "=r"(r0), "=r"(r1), "=r"(r2), "=r"(r3) : "r"(addr))

__device__ __forceinline__ void mma16816(float* d, const uint32_t* a, uint32_t b0, uint32_t b1) {
    asm volatile("mma.sync.aligned.m16n8k16.row.col.f32.bf16.bf16.f32 "
        "{%0,%1,%2,%3}, {%4,%5,%6,%7}, {%8,%9}, {%0,%1,%2,%3};"
        : "+f"(d[0]), "+f"(d[1]), "+f"(d[2]), "+f"(d[3])
        : "r"(a[0]), "r"(a[1]), "r"(a[2]), "r"(a[3]), "r"(b0), "r"(b1));
}

__device__ __forceinline__ void imma16832(int* d, const uint32_t* a, uint32_t b0, uint32_t b1) {
    asm volatile("mma.sync.aligned.m16n8k32.row.col.s32.s8.s8.s32 "
        "{%0,%1,%2,%3}, {%4,%5,%6,%7}, {%8,%9}, {%0,%1,%2,%3};"
        : "+r"(d[0]), "+r"(d[1]), "+r"(d[2]), "+r"(d[3])
        : "r"(a[0]), "r"(a[1]), "r"(a[2]), "r"(a[3]), "r"(b0), "r"(b1));
}

// ---------------- proj weight quant: partial -> fin -> quantize ----------------
__global__ void prep_part_kernel(const float* __restrict__ w) {
    __shared__ double red[256];
    int t = threadIdx.x;
    int base = blockIdx.x * 4096;
    double s = 0.0;
    #pragma unroll 4
    for (int i = t; i < 4096; i += 256) s += (double)fabsf(w[base + i]);
    red[t] = s; __syncthreads();
    for (int o = 128; o > 0; o >>= 1) { if (t < o) red[t] += red[t + o]; __syncthreads(); }
    if (t == 0) g_wsum[blockIdx.x] = red[0];
}
__global__ void prep_fin_kernel() {
    __shared__ double red[64];
    int t = threadIdx.x;
    red[t] = g_wsum[t]; __syncthreads();
    for (int o = 32; o > 0; o >>= 1) { if (t < o) red[t] += red[t + o]; __syncthreads(); }
    if (t == 0) {
        float mean = (float)(red[0] * (1.0 / (double)(CC * CC)));
        g_wdq = fmaxf(mean, 1e-5f);
    }
}
__global__ void prep_quant_kernel(const float* __restrict__ w) {
    int i = blockIdx.x * 1024 + threadIdx.x;
    float sc = 1.0f / g_wdq;
    #pragma unroll
    for (int e = 0; e < 4; ++e) {
        int idx = i + e * 256;
        float q = rintf(w[idx] * sc);
        q = fminf(fmaxf(q, -1.0f), 1.0f);
        g_wq[idx] = (signed char)(int)q;
    }
}

// ---------------- conv weight bf16-split pack ----------------
__global__ void pack_w_kernel(const float* __restrict__ w) {   // w: [co][ci][3]
    int idx = blockIdx.x * 256 + threadIdx.x;
    if (idx >= CC * 1536) return;
    int co = idx / 1536, r = idx % 1536;
    int tap = r / 512, ci = r % 512;
    float f = w[((size_t)co * CC + ci) * 3 + tap];
    __nv_bfloat16 h = __float2bfloat16(f);
    __nv_bfloat16 l = __float2bfloat16(f - __bfloat162float(h));
    g_wq2[(size_t)co * 3072 + r]        = h;
    g_wq2[(size_t)co * 3072 + 1536 + r] = l;
}

// ---------------- activation transpose + bf16-split pack (guard-row layout) --------
__global__ __launch_bounds__(256) void pack_x_kernel(const float* __restrict__ x) {
    __shared__ float xs[128 * 65];
    int b   = blockIdx.z;
    int ci0 = blockIdx.y * 64;
    int l0  = blockIdx.x * 128;
    int t = threadIdx.x;

    for (int it = t; it < 64 * 128; it += 256) {
        int ci = it >> 7, c = it & 127;
        xs[c * 65 + ci] = x[((size_t)b * CC + ci0 + ci) * LL + l0 + c];
    }
    __syncthreads();

    for (int it = t; it < 1024; it += 256) {
        int tok = it >> 3, g = it & 7;
        __align__(16) __nv_bfloat16 hi[8], lo[8];
        #pragma unroll
        for (int e = 0; e < 8; ++e) {
            float f = xs[tok * 65 + g * 8 + e];
            __nv_bfloat16 h = __float2bfloat16(f);
            hi[e] = h;
            lo[e] = __float2bfloat16(f - __bfloat162float(h));
        }
        size_t row = (size_t)b * 1026 + 1 + l0 + tok;
        *(uint4*)(g_bq + row * 1024 + ci0 + g * 8)       = *(const uint4*)hi;
        *(uint4*)(g_bq + row * 1024 + 512 + ci0 + g * 8) = *(const uint4*)lo;
    }

    if (l0 == 0 && t < 16) {
        size_t row = (size_t)b * 1026;
        int col = (t >> 3) * 512 + ci0 + (t & 7) * 8;
        *(uint4*)(g_bq + row * 1024 + col) = make_uint4(0, 0, 0, 0);
    }
    if (l0 == (LL - 128) && t < 16) {
        size_t row = (size_t)b * 1026 + 1025;
        int col = (t >> 3) * 512 + ci0 + (t & 7) * 8;
        *(uint4*)(g_bq + row * 1024 + col) = make_uint4(0, 0, 0, 0);
    }
}

// ---------------- conv GEMM via mma.sync bf16 (3-pass split, fp32 acc) --------
// 128 co x 128 tok tile; 8 warps of 64x32; 3-stage pipeline; 2 blocks/SM; fused BN.
static __device__ __forceinline__ void ld_chunk_c(uint32_t abuf, uint32_t bbuf,
                                                  int idx, int co0, int browb, int t) {
    int p = idx / 24, ch = idx % 24;
    int tap = ch >> 3, cic = ch & 7;
    const __nv_bfloat16* ga = g_wq2 + (size_t)co0 * 3072 + ((p == 2) ? 1536 : 0) + ch * 64;
    const __nv_bfloat16* gb = g_bq + (size_t)(browb + tap) * 1024
                                   + ((p == 1) ? 512 : 0) + cic * 64;
    for (int it = t; it < 1024; it += 256) {
        int row = it >> 3, c = it & 7;
        cp16(abuf + SWZ(row * 128 + c * 16), ga + (size_t)row * 3072 + c * 8);
    }
    for (int it = t; it < 1024; it += 256) {
        int row = it >> 3, c = it & 7;
        cp16(bbuf + SWZ(row * 128 + c * 16), gb + (size_t)row * 1024 + c * 8);
    }
}

__global__ __launch_bounds__(256, 2) void conv_mma_kernel(const float* __restrict__ bias) {
    extern __shared__ char dsm_raw[];
    char* base = (char*)((((size_t)dsm_raw) + 1023) & ~(size_t)1023);
    uint32_t sb = smem_u32(base);
    uint32_t ab[3], bb[3];
    #pragma unroll
    for (int s = 0; s < 3; ++s) { ab[s] = sb + s * 32768; bb[s] = sb + s * 32768 + 16384; }
    __shared__ float bnred[8 * 64 * 2];

    int t = threadIdx.x, wid = t >> 5, lane = t & 31;
    int co0 = blockIdx.x * 128;
    int tok0 = blockIdx.y * 128;
    int bidx = tok0 >> 10;
    int l0 = tok0 & 1023;
    int browb = bidx * 1026 + l0;
    int wco  = (wid & 1) * 64;     // warp covers 64 co (m)
    int wtok = (wid >> 1) * 32;    // warp covers 32 tokens (n)

    float acc[4][4][4];
    #pragma unroll
    for (int i = 0; i < 4; ++i)
        #pragma unroll
        for (int j = 0; j < 4; ++j)
            #pragma unroll
            for (int e = 0; e < 4; ++e) acc[i][j][e] = 0.0f;

    int g = lane >> 3, r = lane & 7;
    uint32_t ao[4], aM[4], bo[2], bM[2];
    #pragma unroll
    for (int mt = 0; mt < 4; ++mt) {
        int row = wco + mt * 16 + (g & 1) * 8 + r;
        uint32_t o = row * 128 + (g >> 1) * 16;
        aM[mt] = (o >> 3) & 0x70; ao[mt] = o;
    }
    #pragma unroll
    for (int nt = 0; nt < 2; ++nt) {
        int row = wtok + nt * 16 + (g >> 1) * 8 + r;
        uint32_t o = row * 128 + (g & 1) * 16;
        bM[nt] = (o >> 3) & 0x70; bo[nt] = o;
    }

    ld_chunk_c(ab[0], bb[0], 0, co0, browb, t); CP_COMMIT();
    ld_chunk_c(ab[1], bb[1], 1, co0, browb, t); CP_COMMIT();

    for (int i = 0; i < 72; ++i) {
        if (i + 1 < 72) CP_WAIT1(); else CP_WAIT0();
        __syncthreads();
        if (i + 2 < 72) {
            int nb = (i + 2) % 3;
            ld_chunk_c(ab[nb], bb[nb], i + 2, co0, browb, t);
            CP_COMMIT();
        }
        int cur = i % 3;
        uint32_t abase = ab[cur], bbase = bb[cur];
        #pragma unroll
        for (int ks = 0; ks < 4; ++ks) {
            uint32_t A[4][4], Bf[2][4];
            #pragma unroll
            for (int mt = 0; mt < 4; ++mt)
                LDSM_X4(A[mt][0], A[mt][1], A[mt][2], A[mt][3],
                        abase + (((ao[mt] + ks * 32)) ^ aM[mt]));
            #pragma unroll
            for (int nt = 0; nt < 2; ++nt)
                LDSM_X4(Bf[nt][0], Bf[nt][1], Bf[nt][2], Bf[nt][3],
                        bbase + (((bo[nt] + ks * 32)) ^ bM[nt]));
            #pragma unroll
            for (int mt = 0; mt < 4; ++mt)
                #pragma unroll
                for (int n8 = 0; n8 < 4; ++n8)
                    mma16816(acc[mt][n8], A[mt],
                             Bf[n8 >> 1][(n8 & 1) * 2], Bf[n8 >> 1][(n8 & 1) * 2 + 1]);
        }
    }
    __syncthreads();

    // ---- epilogue: bias add + store + fused BN partial sums ----
    float cs[4][2], cq[4][2];
    #pragma unroll
    for (int mt = 0; mt < 4; ++mt) { cs[mt][0] = cs[mt][1] = cq[mt][0] = cq[mt][1] = 0.0f; }

    #pragma unroll
    for (int mt = 0; mt < 4; ++mt) {
        int co = co0 + wco + mt * 16 + (lane >> 2);
        float bv0 = bias[co], bv1 = bias[co + 8];
        #pragma unroll
        for (int n8 = 0; n8 < 4; ++n8) {
            int tok = tok0 + wtok + n8 * 8 + (lane & 3) * 2;
            float v0 = acc[mt][n8][0] + bv0;
            float v1 = acc[mt][n8][1] + bv0;
            float v2 = acc[mt][n8][2] + bv1;
            float v3 = acc[mt][n8][3] + bv1;
            g_conv[(size_t)tok * CC + co]           = v0;
            g_conv[(size_t)(tok + 1) * CC + co]     = v1;
            g_conv[(size_t)tok * CC + co + 8]       = v2;
            g_conv[(size_t)(tok + 1) * CC + co + 8] = v3;
            cs[mt][0] += v0 + v1;  cq[mt][0] += v0 * v0 + v1 * v1;
            cs[mt][1] += v2 + v3;  cq[mt][1] += v2 * v2 + v3 * v3;
        }
    }
    #pragma unroll
    for (int off = 1; off <= 2; off <<= 1) {
        #pragma unroll
        for (int mt = 0; mt < 4; ++mt) {
            cs[mt][0] += __shfl_xor_sync(0xffffffff, cs[mt][0], off);
            cs[mt][1] += __shfl_xor_sync(0xffffffff, cs[mt][1], off);
            cq[mt][0] += __shfl_xor_sync(0xffffffff, cq[mt][0], off);
            cq[mt][1] += __shfl_xor_sync(0xffffffff, cq[mt][1], off);
        }
    }
    if ((lane & 3) == 0) {
        #pragma unroll
        for (int mt = 0; mt < 4; ++mt)
            #pragma unroll
            for (int h = 0; h < 2; ++h) {
                int ci = mt * 16 + (lane >> 2) + 8 * h;
                bnred[(wid * 64 + ci) * 2]     = cs[mt][h];
                bnred[(wid * 64 + ci) * 2 + 1] = cq[mt][h];
            }
    }
    __syncthreads();
    {
        // co-half h covers warps {h, h+2, h+4, h+6} (wid&1 == h)
        int half = t >> 7, ci = (t >> 1) & 63, val = t & 1;
        float s = bnred[((half)     * 64 + ci) * 2 + val]
                + bnred[((half + 2) * 64 + ci) * 2 + val]
                + bnred[((half + 4) * 64 + ci) * 2 + val]
                + bnred[((half + 6) * 64 + ci) * 2 + val];
        int co = co0 + half * 64 + ci;
        if (val == 0) g_psf[blockIdx.y * CC + co]  = s;
        else          g_ps2f[blockIdx.y * CC + co] = s;
    }
}

// ---------------- BN finalize: deterministic double reduction over 256 slices ------
__global__ void bn_fin_kernel() {
    int co = threadIdx.x;
    double a = 0.0, b2 = 0.0;
    #pragma unroll 4
    for (int s = 0; s < 256; ++s) {
        a  += (double)g_psf[s * CC + co];
        b2 += (double)g_ps2f[s * CC + co];
    }
    double m = a / (double)NN;
    double var = b2 / (double)NN - m * m;
    g_mean[co] = (float)m;
    g_rstd[co] = (float)(1.0 / sqrt(var + 1e-5));
}

// ---------------- BN apply + GELU + per-token int8 quant (warp per token) ----------------
__global__ __launch_bounds__(256) void quant_kernel(const float* __restrict__ gamma,
                                                    const float* __restrict__ beta) {
    int t = threadIdx.x, w = t >> 5, lane = t & 31;
    size_t token = (size_t)blockIdx.x * 8 + w;
    int c0 = lane * 16;
    float vals[16];
    float mx = 0.0f;
    #pragma unroll
    for (int i = 0; i < 4; ++i) {
        float4 cv = *(const float4*)(g_conv + token * CC + c0 + i * 4);
        float4 m4 = *(const float4*)(g_mean + c0 + i * 4);
        float4 r4 = *(const float4*)(g_rstd + c0 + i * 4);
        float4 gm = *(const float4*)(gamma + c0 + i * 4);
        float4 bt = *(const float4*)(beta + c0 + i * 4);
        float a[4] = { (cv.x - m4.x) * r4.x * gm.x + bt.x,
                       (cv.y - m4.y) * r4.y * gm.y + bt.y,
                       (cv.z - m4.z) * r4.z * gm.z + bt.z,
                       (cv.w - m4.w) * r4.w * gm.w + bt.w };
        #pragma unroll
        for (int e = 0; e < 4; ++e) {
            float gg = gelu_exact(a[e]);
            vals[i * 4 + e] = gg;
            mx = fmaxf(mx, fabsf(gg));
        }
    }
    #pragma unroll
    for (int off = 16; off > 0; off >>= 1)
        mx = fmaxf(mx, __shfl_xor_sync(0xffffffff, mx, off));
    float clip = fmaxf(mx, 1e-5f);
    if (lane == 0) g_stok[token] = clip * (1.0f / 127.0f);
    float sc = 127.0f / clip;
    int pk[4];
    #pragma unroll
    for (int i = 0; i < 4; ++i) {
        int b0 = 0;
        #pragma unroll
        for (int e = 0; e < 4; ++e) {
            float q = rintf(vals[i * 4 + e] * sc);
            q = fminf(fmaxf(q, -128.0f), 127.0f);
            b0 |= ((int)q & 0xff) << (e * 8);
        }
        pk[i] = b0;
    }
    *(int4*)(g_xq + token * CC + c0) = make_int4(pk[0], pk[1], pk[2], pk[3]);
}

// ---------------- int8 proj GEMM via IMMA (exact): 128co x 128tok, 2 blocks/SM -----
static __device__ __forceinline__ void ld_chunk_p(uint32_t abuf, uint32_t bbuf,
                                                  int idx, int co0, int tok0, int t) {
    const signed char* ga = g_wq + (size_t)co0 * 512 + idx * 128;   // A rows = co
    const signed char* gb = g_xq + (size_t)tok0 * 512 + idx * 128;  // B rows = tok
    for (int it = t; it < 1024; it += 256) {
        int row = it >> 3, c = it & 7;
        cp16(abuf + SWZ(row * 128 + c * 16), ga + (size_t)row * 512 + c * 16);
    }
    for (int it = t; it < 1024; it += 256) {
        int row = it >> 3, c = it & 7;
        cp16(bbuf + SWZ(row * 128 + c * 16), gb + (size_t)row * 512 + c * 16);
    }
}

__global__ __launch_bounds__(256) void proj_mma_kernel(const float* __restrict__ xres,
                                                       float* __restrict__ out) {
    extern __shared__ char dsm_raw[];
    char* base = (char*)((((size_t)dsm_raw) + 1023) & ~(size_t)1023);
    uint32_t sb = smem_u32(base);
    uint32_t ab[2] = { sb,             sb + 32768 };
    uint32_t bb[2] = { sb + 16384,     sb + 49152 };

    int t = threadIdx.x, wid = t >> 5, lane = t & 31;
    int co0  = blockIdx.x * 128;
    int tok0 = blockIdx.y * 128;
    int wco  = (wid & 1) * 64;     // warp covers 64 co (m)
    int wtok = (wid >> 1) * 32;    // warp covers 32 tokens (n)

    int acc[4][4][4];
    #pragma unroll
    for (int i = 0; i < 4; ++i)
        #pragma unroll
        for (int j = 0; j < 4; ++j)
            #pragma unroll
            for (int e = 0; e < 4; ++e) acc[i][j][e] = 0;

    int g = lane >> 3, r = lane & 7;
    uint32_t ao[4], aM[4], bo[2], bM[2];
    #pragma unroll
    for (int mt = 0; mt < 4; ++mt) {
        int row = wco + mt * 16 + (g & 1) * 8 + r;
        uint32_t o = row * 128 + (g >> 1) * 16;
        aM[mt] = (o >> 3) & 0x70; ao[mt] = o;
    }
    #pragma unroll
    for (int nt = 0; nt < 2; ++nt) {
        int row = wtok + nt * 16 + (g >> 1) * 8 + r;
        uint32_t o = row * 128 + (g & 1) * 16;
        bM[nt] = (o >> 3) & 0x70; bo[nt] = o;
    }

    ld_chunk_p(ab[0], bb[0], 0, co0, tok0, t);
    CP_COMMIT();

    for (int i = 0; i < 4; ++i) {
        int cur = i & 1;
        if (i + 1 < 4) {
            ld_chunk_p(ab[cur ^ 1], bb[cur ^ 1], i + 1, co0, tok0, t);
            CP_COMMIT();
            CP_WAIT1();
        } else {
            CP_WAIT0();
        }
        __syncthreads();

        uint32_t abase = ab[cur], bbase = bb[cur];
        #pragma unroll
        for (int ks = 0; ks < 4; ++ks) {
            uint32_t A[4][4], Bf[2][4];
            #pragma unroll
            for (int mt = 0; mt < 4; ++mt)
                LDSM_X4(A[mt][0], A[mt][1], A[mt][2], A[mt][3],
                        abase + (((ao[mt] + ks * 32)) ^ aM[mt]));
            #pragma unroll
            for (int nt = 0; nt < 2; ++nt)
                LDSM_X4(Bf[nt][0], Bf[nt][1], Bf[nt][2], Bf[nt][3],
                        bbase + (((bo[nt] + ks * 32)) ^ bM[nt]));
            #pragma unroll
            for (int mt = 0; mt < 4; ++mt)
                #pragma unroll
                for (int n8 = 0; n8 < 4; ++n8)
                    imma16832(acc[mt][n8], A[mt],
                              Bf[n8 >> 1][(n8 & 1) * 2], Bf[n8 >> 1][(n8 & 1) * 2 + 1]);
        }
        __syncthreads();
    }

    // epilogue: acc[mt][n8] = {(co,tok),(co,tok+1),(co+8,tok),(co+8,tok+1)}
    float wdq = g_wdq;
    #pragma unroll
    for (int n8 = 0; n8 < 4; ++n8) {
        int tok = tok0 + wtok + n8 * 8 + (lane & 3) * 2;
        float2 sp = *(const float2*)&g_stok[tok];
        float s0 = sp.x * wdq, s1 = sp.y * wdq;
        int b = tok >> 10, l = tok & 1023;
        #pragma unroll
        for (int mt = 0; mt < 4; ++mt) {
            int co = co0 + wco + mt * 16 + (lane >> 2);
            size_t base0 = (((size_t)b * CC + co) << 10) + l;
            size_t base1 = base0 + ((size_t)8 << 10);
            float2 r0 = *(const float2*)&xres[base0];
            float2 r1 = *(const float2*)&xres[base1];
            float2 o0, o1;
            o0.x = gelu_exact((float)acc[mt][n8][0] * s0) + r0.x;
            o0.y = gelu_exact((float)acc[mt][n8][1] * s1) + r0.y;
            o1.x = gelu_exact((float)acc[mt][n8][2] * s0) + r1.x;
            o1.y = gelu_exact((float)acc[mt][n8][3] * s1) + r1.y;
            *(float2*)&out[base0] = o0;
            *(float2*)&out[base1] = o1;
        }
    }
}

// ---------------- launch ----------------
extern "C" void kernel_launch(void* const* d_in, const int* in_sizes, int n_in,
                              void* d_out, int out_size) {
    (void)in_sizes; (void)n_in; (void)out_size;
    const float* x      = (const float*)d_in[0];   // [32,512,1024]
    const float* conv_w = (const float*)d_in[1];   // [512,512,3]
    const float* conv_b = (const float*)d_in[2];   // [512]
    const float* gamma  = (const float*)d_in[3];   // [512]
    const float* beta   = (const float*)d_in[4];   // [512]
    const float* proj_w = (const float*)d_in[5];   // [512,512]
    float* out = (float*)d_out;

    static int inited = 0;
    static cudaStream_t s2 = 0;
    static cudaEvent_t evF = 0, evJ = 0;
    if (!inited) {
        cudaFuncSetAttribute(conv_mma_kernel, cudaFuncAttributeMaxDynamicSharedMemorySize, 99328);
        cudaFuncSetAttribute(proj_mma_kernel, cudaFuncAttributeMaxDynamicSharedMemorySize, 66560);
        if (cudaStreamCreateWithFlags(&s2, cudaStreamNonBlocking) != cudaSuccess) s2 = 0;
        cudaEventCreateWithFlags(&evF, cudaEventDisableTiming);
        cudaEventCreateWithFlags(&evJ, cudaEventDisableTiming);
        inited = 1;
    }

    // fork: proj-weight prep on side stream (joined before proj)
    cudaEventRecord(evF, 0);
    if (s2) cudaStreamWaitEvent(s2, evF, 0);
    prep_part_kernel<<<64, 256, 0, s2>>>(proj_w);
    prep_fin_kernel<<<1, 64, 0, s2>>>();
    prep_quant_kernel<<<256, 256, 0, s2>>>(proj_w);
    if (s2) cudaEventRecord(evJ, s2);

    pack_w_kernel<<<(CC * 1536 + 255) / 256, 256>>>(conv_w);
    pack_x_kernel<<<dim3(8, 8, 32), 256>>>(x);

    conv_mma_kernel<<<dim3(4, 256), 256, 99328>>>(conv_b);

    bn_fin_kernel<<<1, 512>>>();
    quant_kernel<<<NN / 8, 256>>>(gamma, beta);

    if (s2) cudaStreamWaitEvent(0, evJ, 0);
    proj_mma_kernel<<<dim3(4, 256), 256, 66560>>>(x, out);
}